// round 3
// baseline (speedup 1.0000x reference)
#include <cuda_runtime.h>
#include <math.h>
#include <stdint.h>

#define S_LEN 2048
#define BATCH 4
#define HID 1024
#define NHEADS 16
#define HDIM 64
#define M_ROWS (S_LEN * BATCH)   // 8192
#define QKV_N (3 * HID)          // 3072
#define MASK_VAL (-10000.0f)

// Scratch (allocation-free: device globals)
__device__ float g_mixed[(size_t)M_ROWS * QKV_N];   // 96 MB: QKV output
__device__ float g_ctx[(size_t)M_ROWS * HID];       // 32 MB: attention context
__device__ int   g_mask_is_i32;                     // mask dtype flag

// ---------------------------------------------------------------------------
// Mask dtype detection: jax bool may arrive as int32 (widened) or uint8.
// If the first 1024 int32 words are all 0/1, it's int32; random packed 0/1
// bytes would make words like 0x00010001 (>1) almost immediately.
// ---------------------------------------------------------------------------
__global__ void detect_mask_dtype(const int* __restrict__ mask_as_i32) {
    int ok = 1;
    for (int i = 0; i < 1024; i++) {
        unsigned v = (unsigned)mask_as_i32[i];
        if (v > 1u) { ok = 0; break; }
    }
    g_mask_is_i32 = ok;
}

// ---------------------------------------------------------------------------
// Tiled SGEMM:  C[m][n] = sum_k A[m][k] * B[n][k] + bias[n]
// BM=BN=64, BK=16, 256 threads, 4x4 micro-tile per thread.
// ---------------------------------------------------------------------------
template <int N_DIM, int K_DIM>
__global__ void __launch_bounds__(256)
gemm_nt_bias(const float* __restrict__ A,
             const float* __restrict__ Bm,
             const float* __restrict__ bias,
             float* __restrict__ C) {
    __shared__ float As[16][64];
    __shared__ float Bs[16][64];

    const int m0 = blockIdx.y * 64;
    const int n0 = blockIdx.x * 64;
    const int tid = threadIdx.x;
    const int ty = tid >> 4;        // 0..15
    const int tx = tid & 15;        // 0..15
    const int lrow = tid >> 2;      // 0..63 loader row
    const int lk4  = (tid & 3) * 4; // 0,4,8,12

    float acc[4][4] = {};

    for (int k0 = 0; k0 < K_DIM; k0 += 16) {
        float4 av = *(const float4*)(A  + (size_t)(m0 + lrow) * K_DIM + k0 + lk4);
        float4 bv = *(const float4*)(Bm + (size_t)(n0 + lrow) * K_DIM + k0 + lk4);
        As[lk4 + 0][lrow] = av.x; As[lk4 + 1][lrow] = av.y;
        As[lk4 + 2][lrow] = av.z; As[lk4 + 3][lrow] = av.w;
        Bs[lk4 + 0][lrow] = bv.x; Bs[lk4 + 1][lrow] = bv.y;
        Bs[lk4 + 2][lrow] = bv.z; Bs[lk4 + 3][lrow] = bv.w;
        __syncthreads();

#pragma unroll
        for (int kk = 0; kk < 16; kk++) {
            float a[4], b[4];
#pragma unroll
            for (int i = 0; i < 4; i++) a[i] = As[kk][ty * 4 + i];
#pragma unroll
            for (int j = 0; j < 4; j++) b[j] = Bs[kk][tx * 4 + j];
#pragma unroll
            for (int i = 0; i < 4; i++)
#pragma unroll
                for (int j = 0; j < 4; j++)
                    acc[i][j] = fmaf(a[i], b[j], acc[i][j]);
        }
        __syncthreads();
    }

#pragma unroll
    for (int i = 0; i < 4; i++) {
        const int m = m0 + ty * 4 + i;
#pragma unroll
        for (int j = 0; j < 4; j++) {
            const int n = n0 + tx * 4 + j;
            C[(size_t)m * N_DIM + n] = acc[i][j] + bias[n];
        }
    }
}

// ---------------------------------------------------------------------------
// Flash attention (fp32). Grid: x = q-tile (32), y = b*NH + h (64).
// 256 threads; thread handles row r=tid/4, ctx cols [quad*16, quad*16+16).
// mixed layout: g_mixed[(s*B+b)*3072 + h*192 + {0:q, 64:k, 128:v} + d]
// ---------------------------------------------------------------------------
__global__ void __launch_bounds__(256)
attention_kernel(const void* __restrict__ mask_raw,
                 float* __restrict__ ctx_out) {
    extern __shared__ float smem[];
    float* Qs = smem;                 // [64][64]
    float* Ks = Qs + 64 * 64;         // [64][65] (padded)
    float* Vs = Ks + 64 * 65;         // [64][64]
    float* Ps = Vs + 64 * 64;         // [64][65] probabilities (padded)

    const int qt = blockIdx.x;            // 0..31
    const int bh = blockIdx.y;            // 0..63
    const int b  = bh / NHEADS;
    const int h  = bh % NHEADS;

    const int tid  = threadIdx.x;
    const int r    = tid >> 2;            // 0..63 (row of tile)
    const int quad = tid & 3;
    const int c0   = quad * 16;

    const int mask_i32 = g_mask_is_i32;
    const unsigned char* mask_u8 = (const unsigned char*)mask_raw;
    const int* mask_32 = (const int*)mask_raw;

    // Load Q tile
    {
        const int s = qt * 64 + r;
        const float* src = g_mixed + (size_t)(s * BATCH + b) * QKV_N + h * 192;
#pragma unroll
        for (int i = 0; i < 16; i += 4) {
            float4 v = *(const float4*)(src + c0 + i);
            Qs[r * 64 + c0 + i + 0] = v.x;
            Qs[r * 64 + c0 + i + 1] = v.y;
            Qs[r * 64 + c0 + i + 2] = v.z;
            Qs[r * 64 + c0 + i + 3] = v.w;
        }
    }

    float m_i = -1e30f, l_i = 0.0f;
    float acc[16];
#pragma unroll
    for (int j = 0; j < 16; j++) acc[j] = 0.0f;

    const size_t mask_row_base = ((size_t)b * S_LEN + (size_t)(qt * 64 + r)) * S_LEN;

    for (int kt = 0; kt < 32; kt++) {
        // Load K and V tiles
        {
            const int t = kt * 64 + r;
            const float* src = g_mixed + (size_t)(t * BATCH + b) * QKV_N + h * 192;
#pragma unroll
            for (int i = 0; i < 16; i += 4) {
                float4 kv = *(const float4*)(src + 64 + c0 + i);
                Ks[r * 65 + c0 + i + 0] = kv.x;
                Ks[r * 65 + c0 + i + 1] = kv.y;
                Ks[r * 65 + c0 + i + 2] = kv.z;
                Ks[r * 65 + c0 + i + 3] = kv.w;
                float4 vv = *(const float4*)(src + 128 + c0 + i);
                Vs[r * 64 + c0 + i + 0] = vv.x;
                Vs[r * 64 + c0 + i + 1] = vv.y;
                Vs[r * 64 + c0 + i + 2] = vv.z;
                Vs[r * 64 + c0 + i + 3] = vv.w;
            }
        }
        __syncthreads();

        // Scores for (row r) x (cols c0..c0+15)
        float sc[16];
#pragma unroll
        for (int j = 0; j < 16; j++) sc[j] = 0.0f;
        for (int kk = 0; kk < 64; kk++) {
            const float qv = Qs[r * 64 + kk];
#pragma unroll
            for (int j = 0; j < 16; j++)
                sc[j] = fmaf(qv, Ks[(c0 + j) * 65 + kk], sc[j]);
        }

        // Scale + mask (dtype-adaptive mask load)
        const size_t moff = mask_row_base + (size_t)(kt * 64 + c0);
#pragma unroll
        for (int j = 0; j < 16; j++) {
            const int mv = mask_i32 ? mask_32[moff + j] : (int)mask_u8[moff + j];
            float v = sc[j] * 0.125f;
            sc[j] = mv ? MASK_VAL : v;
        }

        // Row max across 16 local + quad
        float rmax = sc[0];
#pragma unroll
        for (int j = 1; j < 16; j++) rmax = fmaxf(rmax, sc[j]);
        rmax = fmaxf(rmax, __shfl_xor_sync(0xFFFFFFFFu, rmax, 1));
        rmax = fmaxf(rmax, __shfl_xor_sync(0xFFFFFFFFu, rmax, 2));

        const float new_m = fmaxf(m_i, rmax);
        const float corr  = __expf(m_i - new_m);

        // Probabilities
        float lsum = 0.0f;
#pragma unroll
        for (int j = 0; j < 16; j++) {
            float p = __expf(sc[j] - new_m);
            lsum += p;
            Ps[r * 65 + c0 + j] = p;
        }
        lsum += __shfl_xor_sync(0xFFFFFFFFu, lsum, 1);
        lsum += __shfl_xor_sync(0xFFFFFFFFu, lsum, 2);

        l_i = l_i * corr + lsum;
        m_i = new_m;

        __syncthreads();

        // ctx update
#pragma unroll
        for (int j = 0; j < 16; j++) acc[j] *= corr;
        for (int kk = 0; kk < 64; kk++) {
            const float p = Ps[r * 65 + kk];
#pragma unroll
            for (int j = 0; j < 16; j++)
                acc[j] = fmaf(p, Vs[kk * 64 + c0 + j], acc[j]);
        }
        __syncthreads();
    }

    // Write normalized context
    const float inv = 1.0f / l_i;
    const int s = qt * 64 + r;
    float* dst = g_ctx + (size_t)(s * BATCH + b) * HID + h * HDIM + c0;
#pragma unroll
    for (int j = 0; j < 16; j++) dst[j] = acc[j] * inv;
}

// ---------------------------------------------------------------------------
// Launch
// ---------------------------------------------------------------------------
extern "C" void kernel_launch(void* const* d_in, const int* in_sizes, int n_in,
                              void* d_out, int out_size) {
    const float* hs      = (const float*)d_in[0];
    const void*  mask    = d_in[1];
    const float* W_qkv   = (const float*)d_in[2];
    const float* b_qkv   = (const float*)d_in[3];
    const float* W_dense = (const float*)d_in[4];
    const float* b_dense = (const float*)d_in[5];
    float* out = (float*)d_out;

    float* mixed;
    float* ctx;
    cudaGetSymbolAddress((void**)&mixed, g_mixed);
    cudaGetSymbolAddress((void**)&ctx, g_ctx);

    // 0) Detect mask dtype (bool may arrive as int32 or uint8)
    detect_mask_dtype<<<1, 1>>>((const int*)mask);

    // 1) QKV GEMM: [8192,1024] x [3072,1024]^T -> [8192,3072]
    {
        dim3 grid(QKV_N / 64, M_ROWS / 64);
        gemm_nt_bias<QKV_N, HID><<<grid, 256>>>(hs, W_qkv, b_qkv, mixed);
    }

    // 2) Flash attention -> ctx [8192,1024]
    {
        const int smem_bytes = (64 * 64 + 64 * 65 + 64 * 64 + 64 * 65) * sizeof(float);
        cudaFuncSetAttribute(attention_kernel,
                             cudaFuncAttributeMaxDynamicSharedMemorySize, smem_bytes);
        dim3 grid(S_LEN / 64, BATCH * NHEADS);
        attention_kernel<<<grid, 256, smem_bytes>>>(mask, ctx);
    }

    // 3) Dense GEMM: [8192,1024] x [1024,1024]^T -> out [8192,1024]
    {
        dim3 grid(HID / 64, M_ROWS / 64);
        gemm_nt_bias<HID, HID><<<grid, 256>>>(ctx, W_dense, b_dense, out);
    }
}

// round 4
// speedup vs baseline: 2.5774x; 2.5774x over previous
#include <cuda_runtime.h>
#include <math.h>
#include <stdint.h>

#define S_LEN 2048
#define BATCH 4
#define HID 1024
#define NHEADS 16
#define HDIM 64
#define M_ROWS (S_LEN * BATCH)   // 8192
#define QKV_N (3 * HID)          // 3072
#define MASK_VAL (-10000.0f)

// Scratch (allocation-free: device globals)
__device__ float g_mixed[(size_t)M_ROWS * QKV_N];   // 96 MB: QKV output
__device__ float g_ctx[(size_t)M_ROWS * HID];       // 32 MB: attention context
__device__ int   g_mask_is_i32;                     // mask dtype flag

// ---------------------------------------------------------------------------
// Mask dtype detection (unchanged — verified working)
// ---------------------------------------------------------------------------
__global__ void detect_mask_dtype(const int* __restrict__ mask_as_i32) {
    int ok = 1;
    for (int i = 0; i < 1024; i++) {
        unsigned v = (unsigned)mask_as_i32[i];
        if (v > 1u) { ok = 0; break; }
    }
    g_mask_is_i32 = ok;
}

// ---------------------------------------------------------------------------
// Tiled SGEMM (unchanged — measured 82% of FFMA ceiling)
// ---------------------------------------------------------------------------
template <int N_DIM, int K_DIM>
__global__ void __launch_bounds__(256)
gemm_nt_bias(const float* __restrict__ A,
             const float* __restrict__ Bm,
             const float* __restrict__ bias,
             float* __restrict__ C) {
    __shared__ float As[16][64];
    __shared__ float Bs[16][64];

    const int m0 = blockIdx.y * 64;
    const int n0 = blockIdx.x * 64;
    const int tid = threadIdx.x;
    const int ty = tid >> 4;
    const int tx = tid & 15;
    const int lrow = tid >> 2;
    const int lk4  = (tid & 3) * 4;

    float acc[4][4] = {};

    for (int k0 = 0; k0 < K_DIM; k0 += 16) {
        float4 av = *(const float4*)(A  + (size_t)(m0 + lrow) * K_DIM + k0 + lk4);
        float4 bv = *(const float4*)(Bm + (size_t)(n0 + lrow) * K_DIM + k0 + lk4);
        As[lk4 + 0][lrow] = av.x; As[lk4 + 1][lrow] = av.y;
        As[lk4 + 2][lrow] = av.z; As[lk4 + 3][lrow] = av.w;
        Bs[lk4 + 0][lrow] = bv.x; Bs[lk4 + 1][lrow] = bv.y;
        Bs[lk4 + 2][lrow] = bv.z; Bs[lk4 + 3][lrow] = bv.w;
        __syncthreads();

#pragma unroll
        for (int kk = 0; kk < 16; kk++) {
            float a[4], b[4];
#pragma unroll
            for (int i = 0; i < 4; i++) a[i] = As[kk][ty * 4 + i];
#pragma unroll
            for (int j = 0; j < 4; j++) b[j] = Bs[kk][tx * 4 + j];
#pragma unroll
            for (int i = 0; i < 4; i++)
#pragma unroll
                for (int j = 0; j < 4; j++)
                    acc[i][j] = fmaf(a[i], b[j], acc[i][j]);
        }
        __syncthreads();
    }

#pragma unroll
    for (int i = 0; i < 4; i++) {
        const int m = m0 + ty * 4 + i;
#pragma unroll
        for (int j = 0; j < 4; j++) {
            const int n = n0 + tx * 4 + j;
            C[(size_t)m * N_DIM + n] = acc[i][j] + bias[n];
        }
    }
}

// ---------------------------------------------------------------------------
// Flash attention v2: 4x4 register micro-tile, vectorized smem access.
// Grid: x = q-tile (32), y = b*NH + h (64). 256 threads = 16x16 grid.
// Thread (ty,tx): score/ctx block rows [ty*4, ty*4+4) x cols [tx*4, tx*4+4).
// Smem layouts: Qs[d][row], Ks[d][col] (d-major), Vs[t][d], Ps[t][row].
// Row softmax reductions: rows live in 16-lane half-warps -> shfl_xor 1,2,4,8.
// ---------------------------------------------------------------------------
#define PS_STRIDE 68

__global__ void __launch_bounds__(256)
attention_kernel(const void* __restrict__ mask_raw,
                 float* __restrict__ ctx_out) {
    extern __shared__ float smem[];
    float* Qs = smem;                    // [64 d][64 row]
    float* Ks = Qs + 64 * 64;            // [64 d][64 col]
    float* Vs = Ks + 64 * 64;            // [64 t][64 d]
    float* Ps = Vs + 64 * 64;            // [64 t][PS_STRIDE rows]

    const int qt = blockIdx.x;
    const int bh = blockIdx.y;
    const int b  = bh / NHEADS;
    const int h  = bh % NHEADS;

    const int tid = threadIdx.x;
    const int tx  = tid & 15;
    const int ty  = tid >> 4;
    const int r0  = ty * 4;              // local rows
    const int c0  = tx * 4;              // local cols / dims

    const int mask_i32 = g_mask_is_i32;
    const unsigned char* mask_u8 = (const unsigned char*)mask_raw;
    const int* mask_32 = (const int*)mask_raw;

    // ---- Load Q tile into Qs[d][row] (transposed) ----
#pragma unroll
    for (int it = 0; it < 4; it++) {
        const int idx = tid + 256 * it;        // 0..1023
        const int row = idx & 63;
        const int d4  = (idx >> 6) * 4;
        const float* src = g_mixed + (size_t)((qt * 64 + row) * BATCH + b) * QKV_N
                         + h * 192 + d4;
        float4 v = *(const float4*)src;
        Qs[(d4 + 0) * 64 + row] = v.x;
        Qs[(d4 + 1) * 64 + row] = v.y;
        Qs[(d4 + 2) * 64 + row] = v.z;
        Qs[(d4 + 3) * 64 + row] = v.w;
    }

    float m_i[4], l_i[4];
    float acc[4][4];
#pragma unroll
    for (int i = 0; i < 4; i++) {
        m_i[i] = -1e30f; l_i[i] = 0.0f;
#pragma unroll
        for (int j = 0; j < 4; j++) acc[i][j] = 0.0f;
    }

    const size_t mask_base = (size_t)b * S_LEN * S_LEN
                           + (size_t)(qt * 64 + r0) * S_LEN;

    for (int kt = 0; kt < 32; kt++) {
        // ---- Load K tile -> Ks[d][col], V tile -> Vs[t][d] ----
#pragma unroll
        for (int it = 0; it < 4; it++) {
            const int idx = tid + 256 * it;
            // K: transposed store
            {
                const int col = idx & 63;
                const int d4  = (idx >> 6) * 4;
                const float* src = g_mixed + (size_t)((kt * 64 + col) * BATCH + b) * QKV_N
                                 + h * 192 + 64 + d4;
                float4 v = *(const float4*)src;
                Ks[(d4 + 0) * 64 + col] = v.x;
                Ks[(d4 + 1) * 64 + col] = v.y;
                Ks[(d4 + 2) * 64 + col] = v.z;
                Ks[(d4 + 3) * 64 + col] = v.w;
            }
            // V: natural layout, float4 copy
            {
                const int t  = idx >> 4;
                const int d4 = (idx & 15) * 4;
                const float* src = g_mixed + (size_t)((kt * 64 + t) * BATCH + b) * QKV_N
                                 + h * 192 + 128 + d4;
                *(float4*)&Vs[t * 64 + d4] = *(const float4*)src;
            }
        }
        __syncthreads();

        // ---- Scores: sc[i][j] = sum_d Q[r0+i][d] * K[c0+j][d] ----
        float sc[4][4];
#pragma unroll
        for (int i = 0; i < 4; i++)
#pragma unroll
            for (int j = 0; j < 4; j++) sc[i][j] = 0.0f;

#pragma unroll 8
        for (int kk = 0; kk < 64; kk++) {
            const float4 qv = *(const float4*)&Qs[kk * 64 + r0];
            const float4 kv = *(const float4*)&Ks[kk * 64 + c0];
            const float qa[4] = {qv.x, qv.y, qv.z, qv.w};
            const float kb[4] = {kv.x, kv.y, kv.z, kv.w};
#pragma unroll
            for (int i = 0; i < 4; i++)
#pragma unroll
                for (int j = 0; j < 4; j++)
                    sc[i][j] = fmaf(qa[i], kb[j], sc[i][j]);
        }

        // ---- Scale + mask ----
        const size_t kcol0 = (size_t)(kt * 64 + c0);
#pragma unroll
        for (int i = 0; i < 4; i++) {
            const size_t off = mask_base + (size_t)i * S_LEN + kcol0;
            int mv[4];
            if (mask_i32) {
                const int4 m4 = *(const int4*)(mask_32 + off);
                mv[0] = m4.x; mv[1] = m4.y; mv[2] = m4.z; mv[3] = m4.w;
            } else {
                const uchar4 m4 = *(const uchar4*)(mask_u8 + off);
                mv[0] = m4.x; mv[1] = m4.y; mv[2] = m4.z; mv[3] = m4.w;
            }
#pragma unroll
            for (int j = 0; j < 4; j++) {
                const float v = sc[i][j] * 0.125f;
                sc[i][j] = mv[j] ? MASK_VAL : v;
            }
        }

        // ---- Online softmax (per row, across 16 tx lanes in half-warp) ----
        float p[4][4];
#pragma unroll
        for (int i = 0; i < 4; i++) {
            float rmax = fmaxf(fmaxf(sc[i][0], sc[i][1]), fmaxf(sc[i][2], sc[i][3]));
            rmax = fmaxf(rmax, __shfl_xor_sync(0xFFFFFFFFu, rmax, 1));
            rmax = fmaxf(rmax, __shfl_xor_sync(0xFFFFFFFFu, rmax, 2));
            rmax = fmaxf(rmax, __shfl_xor_sync(0xFFFFFFFFu, rmax, 4));
            rmax = fmaxf(rmax, __shfl_xor_sync(0xFFFFFFFFu, rmax, 8));

            const float newm = fmaxf(m_i[i], rmax);
            const float corr = __expf(m_i[i] - newm);
            m_i[i] = newm;

            float lsum = 0.0f;
#pragma unroll
            for (int j = 0; j < 4; j++) {
                p[i][j] = __expf(sc[i][j] - newm);
                lsum += p[i][j];
            }
            lsum += __shfl_xor_sync(0xFFFFFFFFu, lsum, 1);
            lsum += __shfl_xor_sync(0xFFFFFFFFu, lsum, 2);
            lsum += __shfl_xor_sync(0xFFFFFFFFu, lsum, 4);
            lsum += __shfl_xor_sync(0xFFFFFFFFu, lsum, 8);

            l_i[i] = l_i[i] * corr + lsum;
#pragma unroll
            for (int j = 0; j < 4; j++) acc[i][j] *= corr;
        }

        // ---- Write P transposed: Ps[t][row] ----
#pragma unroll
        for (int j = 0; j < 4; j++) {
            *(float4*)&Ps[(c0 + j) * PS_STRIDE + r0] =
                make_float4(p[0][j], p[1][j], p[2][j], p[3][j]);
        }
        __syncthreads();

        // ---- ctx += P @ V : acc[i][j] += sum_t P[t][r0+i] * V[t][c0+j] ----
#pragma unroll 8
        for (int t = 0; t < 64; t++) {
            const float4 pv = *(const float4*)&Ps[t * PS_STRIDE + r0];
            const float4 vv = *(const float4*)&Vs[t * 64 + c0];
            const float pa[4] = {pv.x, pv.y, pv.z, pv.w};
            const float vb[4] = {vv.x, vv.y, vv.z, vv.w};
#pragma unroll
            for (int i = 0; i < 4; i++)
#pragma unroll
                for (int j = 0; j < 4; j++)
                    acc[i][j] = fmaf(pa[i], vb[j], acc[i][j]);
        }
        __syncthreads();
    }

    // ---- Normalize and write ctx: g_ctx[(s*B+b)*1024 + h*64 + d] ----
#pragma unroll
    for (int i = 0; i < 4; i++) {
        const float inv = 1.0f / l_i[i];
        const int s = qt * 64 + r0 + i;
        float* dst = g_ctx + (size_t)(s * BATCH + b) * HID + h * HDIM + c0;
        *(float4*)dst = make_float4(acc[i][0] * inv, acc[i][1] * inv,
                                    acc[i][2] * inv, acc[i][3] * inv);
    }
}

// ---------------------------------------------------------------------------
// Launch
// ---------------------------------------------------------------------------
extern "C" void kernel_launch(void* const* d_in, const int* in_sizes, int n_in,
                              void* d_out, int out_size) {
    const float* hs      = (const float*)d_in[0];
    const void*  mask    = d_in[1];
    const float* W_qkv   = (const float*)d_in[2];
    const float* b_qkv   = (const float*)d_in[3];
    const float* W_dense = (const float*)d_in[4];
    const float* b_dense = (const float*)d_in[5];
    float* out = (float*)d_out;

    float* mixed;
    float* ctx;
    cudaGetSymbolAddress((void**)&mixed, g_mixed);
    cudaGetSymbolAddress((void**)&ctx, g_ctx);

    // 0) Detect mask dtype
    detect_mask_dtype<<<1, 1>>>((const int*)mask);

    // 1) QKV GEMM: [8192,1024] x [3072,1024]^T -> [8192,3072]
    {
        dim3 grid(QKV_N / 64, M_ROWS / 64);
        gemm_nt_bias<QKV_N, HID><<<grid, 256>>>(hs, W_qkv, b_qkv, mixed);
    }

    // 2) Flash attention v2 -> ctx [8192,1024]
    {
        const int smem_bytes = (64 * 64 * 3 + 64 * PS_STRIDE) * sizeof(float);
        cudaFuncSetAttribute(attention_kernel,
                             cudaFuncAttributeMaxDynamicSharedMemorySize, smem_bytes);
        dim3 grid(S_LEN / 64, BATCH * NHEADS);
        attention_kernel<<<grid, 256, smem_bytes>>>(mask, ctx);
    }

    // 3) Dense GEMM: [8192,1024] x [1024,1024]^T -> out [8192,1024]
    {
        dim3 grid(HID / 64, M_ROWS / 64);
        gemm_nt_bias<HID, HID><<<grid, 256>>>(ctx, W_dense, b_dense, out);
    }
}

// round 7
// speedup vs baseline: 3.9405x; 1.5289x over previous
#include <cuda_runtime.h>
#include <cuda_bf16.h>
#include <math.h>
#include <stdint.h>

#define S_LEN 2048
#define BATCH 4
#define HID 1024
#define NHEADS 16
#define HDIM 64
#define M_ROWS (S_LEN * BATCH)   // 8192
#define QKV_N (3 * HID)          // 3072
#define GK HID                   // K dim of both GEMMs = 1024
#define MASK_VAL (-10000.0f)

// ---------------- scratch (allocation-free: device globals) ----------------
__device__ float g_mixed[(size_t)M_ROWS * QKV_N];           // 96 MB
__device__ float g_ctx[(size_t)M_ROWS * HID];               // 32 MB
__device__ int   g_mask_is_i32;

__device__ __align__(16) __nv_bfloat16 g_pA_hi[(size_t)M_ROWS * HID];
__device__ __align__(16) __nv_bfloat16 g_pA_lo[(size_t)M_ROWS * HID];
__device__ __align__(16) __nv_bfloat16 g_pWq_hi[(size_t)QKV_N * HID];
__device__ __align__(16) __nv_bfloat16 g_pWq_lo[(size_t)QKV_N * HID];
__device__ __align__(16) __nv_bfloat16 g_pWd_hi[(size_t)HID * HID];
__device__ __align__(16) __nv_bfloat16 g_pWd_lo[(size_t)HID * HID];

// ---------------- helpers ----------------
__device__ __forceinline__ uint32_t smem_to_u32(const void* p) {
    uint32_t a;
    asm("{ .reg .u64 t; cvta.to.shared.u64 t, %1; cvt.u32.u64 %0, t; }" : "=r"(a) : "l"(p));
    return a;
}

__device__ __forceinline__ void cp_async16(uint32_t dst, const void* src) {
    asm volatile("cp.async.cg.shared.global [%0], [%1], 16;" :: "r"(dst), "l"(src));
}
#define CP_COMMIT() asm volatile("cp.async.commit_group;" ::: "memory")
#define CP_WAIT0()  asm volatile("cp.async.wait_group 0;" ::: "memory")

__device__ __forceinline__ void ldmx4(uint32_t* r, uint32_t addr) {
    asm volatile("ldmatrix.sync.aligned.m8n8.x4.shared.b16 {%0,%1,%2,%3}, [%4];"
                 : "=r"(r[0]), "=r"(r[1]), "=r"(r[2]), "=r"(r[3]) : "r"(addr));
}

__device__ __forceinline__ void mma16816(float* c, const uint32_t* a, uint32_t b0, uint32_t b1) {
    asm volatile(
        "mma.sync.aligned.m16n8k16.row.col.f32.bf16.bf16.f32 "
        "{%0,%1,%2,%3}, {%4,%5,%6,%7}, {%8,%9}, {%0,%1,%2,%3};"
        : "+f"(c[0]), "+f"(c[1]), "+f"(c[2]), "+f"(c[3])
        : "r"(a[0]), "r"(a[1]), "r"(a[2]), "r"(a[3]), "r"(b0), "r"(b1));
}

// ---------------------------------------------------------------------------
// Mask dtype detection (verified working)
// ---------------------------------------------------------------------------
__global__ void detect_mask_dtype(const int* __restrict__ mask_as_i32) {
    int ok = 1;
    for (int i = 0; i < 1024; i++) {
        unsigned v = (unsigned)mask_as_i32[i];
        if (v > 1u) { ok = 0; break; }
    }
    g_mask_is_i32 = ok;
}

// ---------------------------------------------------------------------------
// Pack fp32 -> hi/lo bf16 (row-major, flat). One thread per 4 elements.
// ---------------------------------------------------------------------------
__global__ void __launch_bounds__(256)
pack_hilo(const float* __restrict__ src, __nv_bfloat16* __restrict__ hi,
          __nv_bfloat16* __restrict__ lo) {
    const size_t idx = (size_t)blockIdx.x * 256 + threadIdx.x;
    const float4 v = *(const float4*)(src + idx * 4);
    __align__(8) __nv_bfloat16 h[4], l[4];
    const float f[4] = {v.x, v.y, v.z, v.w};
#pragma unroll
    for (int j = 0; j < 4; j++) {
        h[j] = __float2bfloat16(f[j]);
        l[j] = __float2bfloat16(f[j] - __bfloat162float(h[j]));
    }
    *(uint2*)(hi + idx * 4) = *(const uint2*)h;
    *(uint2*)(lo + idx * 4) = *(const uint2*)l;
}

// ---------------------------------------------------------------------------
// bf16 hi/lo GEMM via mma.sync (HMMA): C[m][n] = sum_k A[m][k]*B[n][k]+bias[n]
// CTA 128x128, 8 warps (4m x 2n), warp tile 32x64, BK=32, double-buffered
// cp.async. smem pitch 80B (conflict-free ldmatrix).
// ---------------------------------------------------------------------------
#define GP 80                       // smem row pitch bytes (32 bf16 + 8 pad)
#define GT_TILE (128 * GP)          // 10240 B per 128x32 tile
#define GT_STAGE (4 * GT_TILE)      // Ah, Al, Bh, Bl
#define GT_SMEM (2 * GT_STAGE)      // 81920 B

__global__ void __launch_bounds__(256)
gemm_mma(const __nv_bfloat16* __restrict__ Ahi, const __nv_bfloat16* __restrict__ Alo,
         const __nv_bfloat16* __restrict__ Bhi, const __nv_bfloat16* __restrict__ Blo,
         const float* __restrict__ bias, float* __restrict__ C, int n_dim) {
    extern __shared__ __align__(1024) char smem[];
    const uint32_t sb = smem_to_u32(smem);
    const int tid = threadIdx.x;
    const int bx = blockIdx.x, by = blockIdx.y;
    const int w = tid >> 5, l = tid & 31;
    const int wm = w >> 1, wn = w & 1;        // 4 x 2 warp grid

    // per-thread copy coordinates (2 chunks of 16B per tile per stage)
    const int c0row = tid >> 2,        c0col = tid & 3;
    const int c1row = (tid + 256) >> 2, c1col = (tid + 256) & 3;

    const __nv_bfloat16* srcs[4] = {Ahi, Alo, Bhi, Blo};
    const size_t rowbase[4] = {(size_t)by * 128, (size_t)by * 128,
                               (size_t)bx * 128, (size_t)bx * 128};

    float acc[2][8][4];
#pragma unroll
    for (int i = 0; i < 2; i++)
#pragma unroll
        for (int j = 0; j < 8; j++)
#pragma unroll
            for (int q = 0; q < 4; q++) acc[i][j][q] = 0.0f;

    // ldmatrix lane addressing offsets
    const uint32_t a_lane = (uint32_t)(l & 15) * GP + ((l >> 4) & 1) * 16;
    const uint32_t b_lane = (uint32_t)((l & 7) + ((l >> 4) & 1) * 8) * GP + ((l >> 3) & 1) * 16;

    // issue copies for stage s, k offset k0 (elements)
    auto issue = [&](int s, int k0) {
        const uint32_t st = sb + s * GT_STAGE;
#pragma unroll
        for (int t = 0; t < 4; t++) {
            const __nv_bfloat16* base = srcs[t] + (rowbase[t]) * GK + k0;
            cp_async16(st + t * GT_TILE + c0row * GP + c0col * 16,
                       base + (size_t)c0row * GK + c0col * 8);
            cp_async16(st + t * GT_TILE + c1row * GP + c1col * 16,
                       base + (size_t)c1row * GK + c1col * 8);
        }
        CP_COMMIT();
    };

    issue(0, 0);

    for (int kt = 0; kt < GK / 32; kt++) {
        const int s = kt & 1;
        CP_WAIT0();
        __syncthreads();
        if (kt + 1 < GK / 32) issue(s ^ 1, (kt + 1) * 32);

        const uint32_t st = sb + s * GT_STAGE;
#pragma unroll
        for (int ks = 0; ks < 2; ks++) {
            const uint32_t kb = ks * 32;          // 16 bf16 = 32 bytes
            uint32_t ah[2][4], al[2][4], bh[4][4], bl[4][4];
#pragma unroll
            for (int mi = 0; mi < 2; mi++) {
                const uint32_t ao = (uint32_t)(wm * 32 + mi * 16) * GP + kb + a_lane;
                ldmx4(ah[mi], st + ao);
                ldmx4(al[mi], st + GT_TILE + ao);
            }
#pragma unroll
            for (int bi = 0; bi < 4; bi++) {
                const uint32_t bo = (uint32_t)(wn * 64 + bi * 16) * GP + kb + b_lane;
                ldmx4(bh[bi], st + 2 * GT_TILE + bo);
                ldmx4(bl[bi], st + 3 * GT_TILE + bo);
            }
#pragma unroll
            for (int mi = 0; mi < 2; mi++)
#pragma unroll
                for (int bi = 0; bi < 4; bi++)
#pragma unroll
                    for (int t = 0; t < 2; t++) {
                        float* c = acc[mi][bi * 2 + t];
                        mma16816(c, ah[mi], bh[bi][t * 2], bh[bi][t * 2 + 1]);
                        mma16816(c, al[mi], bh[bi][t * 2], bh[bi][t * 2 + 1]);
                        mma16816(c, ah[mi], bl[bi][t * 2], bl[bi][t * 2 + 1]);
                    }
        }
        __syncthreads();
    }

    // epilogue: C fragment m16n8: lane l -> rows l/4, l/4+8; cols 2*(l%4)+{0,1}
    const int mg = by * 128 + wm * 32 + (l >> 2);
    const int ng0 = bx * 128 + wn * 64 + (l & 3) * 2;
#pragma unroll
    for (int mi = 0; mi < 2; mi++) {
#pragma unroll
        for (int ni = 0; ni < 8; ni++) {
            const int n = ng0 + ni * 8;
            const float2 bv = *(const float2*)(bias + n);
            const int m0 = mg + mi * 16;
            float* p0 = C + (size_t)m0 * n_dim + n;
            float* p1 = C + (size_t)(m0 + 8) * n_dim + n;
            *(float2*)p0 = make_float2(acc[mi][ni][0] + bv.x, acc[mi][ni][1] + bv.y);
            *(float2*)p1 = make_float2(acc[mi][ni][2] + bv.x, acc[mi][ni][3] + bv.y);
        }
    }
}

// ---------------------------------------------------------------------------
// Flash attention v2 (unchanged — measured ~93% of fp32 FMA floor)
// ---------------------------------------------------------------------------
#define PS_STRIDE 68

__global__ void __launch_bounds__(256)
attention_kernel(const void* __restrict__ mask_raw,
                 float* __restrict__ ctx_out) {
    extern __shared__ __align__(1024) char smem[];
    float* fsm = (float*)smem;
    float* Qs = fsm;
    float* Ks = Qs + 64 * 64;
    float* Vs = Ks + 64 * 64;
    float* Ps = Vs + 64 * 64;

    const int qt = blockIdx.x;
    const int bh = blockIdx.y;
    const int b  = bh / NHEADS;
    const int h  = bh % NHEADS;

    const int tid = threadIdx.x;
    const int tx  = tid & 15;
    const int ty  = tid >> 4;
    const int r0  = ty * 4;
    const int c0  = tx * 4;

    const int mask_i32 = g_mask_is_i32;
    const unsigned char* mask_u8 = (const unsigned char*)mask_raw;
    const int* mask_32 = (const int*)mask_raw;

#pragma unroll
    for (int it = 0; it < 4; it++) {
        const int idx = tid + 256 * it;
        const int row = idx & 63;
        const int d4  = (idx >> 6) * 4;
        const float* src = g_mixed + (size_t)((qt * 64 + row) * BATCH + b) * QKV_N
                         + h * 192 + d4;
        float4 v = *(const float4*)src;
        Qs[(d4 + 0) * 64 + row] = v.x;
        Qs[(d4 + 1) * 64 + row] = v.y;
        Qs[(d4 + 2) * 64 + row] = v.z;
        Qs[(d4 + 3) * 64 + row] = v.w;
    }

    float m_i[4], l_i[4];
    float acc[4][4];
#pragma unroll
    for (int i = 0; i < 4; i++) {
        m_i[i] = -1e30f; l_i[i] = 0.0f;
#pragma unroll
        for (int j = 0; j < 4; j++) acc[i][j] = 0.0f;
    }

    const size_t mask_base = (size_t)b * S_LEN * S_LEN
                           + (size_t)(qt * 64 + r0) * S_LEN;

    for (int kt = 0; kt < 32; kt++) {
#pragma unroll
        for (int it = 0; it < 4; it++) {
            const int idx = tid + 256 * it;
            {
                const int col = idx & 63;
                const int d4  = (idx >> 6) * 4;
                const float* src = g_mixed + (size_t)((kt * 64 + col) * BATCH + b) * QKV_N
                                 + h * 192 + 64 + d4;
                float4 v = *(const float4*)src;
                Ks[(d4 + 0) * 64 + col] = v.x;
                Ks[(d4 + 1) * 64 + col] = v.y;
                Ks[(d4 + 2) * 64 + col] = v.z;
                Ks[(d4 + 3) * 64 + col] = v.w;
            }
            {
                const int t  = idx >> 4;
                const int d4 = (idx & 15) * 4;
                const float* src = g_mixed + (size_t)((kt * 64 + t) * BATCH + b) * QKV_N
                                 + h * 192 + 128 + d4;
                *(float4*)&Vs[t * 64 + d4] = *(const float4*)src;
            }
        }
        __syncthreads();

        float sc[4][4];
#pragma unroll
        for (int i = 0; i < 4; i++)
#pragma unroll
            for (int j = 0; j < 4; j++) sc[i][j] = 0.0f;

#pragma unroll 8
        for (int kk = 0; kk < 64; kk++) {
            const float4 qv = *(const float4*)&Qs[kk * 64 + r0];
            const float4 kv = *(const float4*)&Ks[kk * 64 + c0];
            const float qa[4] = {qv.x, qv.y, qv.z, qv.w};
            const float kb[4] = {kv.x, kv.y, kv.z, kv.w};
#pragma unroll
            for (int i = 0; i < 4; i++)
#pragma unroll
                for (int j = 0; j < 4; j++)
                    sc[i][j] = fmaf(qa[i], kb[j], sc[i][j]);
        }

        const size_t kcol0 = (size_t)(kt * 64 + c0);
#pragma unroll
        for (int i = 0; i < 4; i++) {
            const size_t off = mask_base + (size_t)i * S_LEN + kcol0;
            int mv[4];
            if (mask_i32) {
                const int4 m4 = *(const int4*)(mask_32 + off);
                mv[0] = m4.x; mv[1] = m4.y; mv[2] = m4.z; mv[3] = m4.w;
            } else {
                const uchar4 m4 = *(const uchar4*)(mask_u8 + off);
                mv[0] = m4.x; mv[1] = m4.y; mv[2] = m4.z; mv[3] = m4.w;
            }
#pragma unroll
            for (int j = 0; j < 4; j++) {
                const float v = sc[i][j] * 0.125f;
                sc[i][j] = mv[j] ? MASK_VAL : v;
            }
        }

        float p[4][4];
#pragma unroll
        for (int i = 0; i < 4; i++) {
            float rmax = fmaxf(fmaxf(sc[i][0], sc[i][1]), fmaxf(sc[i][2], sc[i][3]));
            rmax = fmaxf(rmax, __shfl_xor_sync(0xFFFFFFFFu, rmax, 1));
            rmax = fmaxf(rmax, __shfl_xor_sync(0xFFFFFFFFu, rmax, 2));
            rmax = fmaxf(rmax, __shfl_xor_sync(0xFFFFFFFFu, rmax, 4));
            rmax = fmaxf(rmax, __shfl_xor_sync(0xFFFFFFFFu, rmax, 8));

            const float newm = fmaxf(m_i[i], rmax);
            const float corr = __expf(m_i[i] - newm);
            m_i[i] = newm;

            float lsum = 0.0f;
#pragma unroll
            for (int j = 0; j < 4; j++) {
                p[i][j] = __expf(sc[i][j] - newm);
                lsum += p[i][j];
            }
            lsum += __shfl_xor_sync(0xFFFFFFFFu, lsum, 1);
            lsum += __shfl_xor_sync(0xFFFFFFFFu, lsum, 2);
            lsum += __shfl_xor_sync(0xFFFFFFFFu, lsum, 4);
            lsum += __shfl_xor_sync(0xFFFFFFFFu, lsum, 8);

            l_i[i] = l_i[i] * corr + lsum;
#pragma unroll
            for (int j = 0; j < 4; j++) acc[i][j] *= corr;
        }

#pragma unroll
        for (int j = 0; j < 4; j++) {
            *(float4*)&Ps[(c0 + j) * PS_STRIDE + r0] =
                make_float4(p[0][j], p[1][j], p[2][j], p[3][j]);
        }
        __syncthreads();

#pragma unroll 8
        for (int t = 0; t < 64; t++) {
            const float4 pv = *(const float4*)&Ps[t * PS_STRIDE + r0];
            const float4 vv = *(const float4*)&Vs[t * 64 + c0];
            const float pa[4] = {pv.x, pv.y, pv.z, pv.w};
            const float vb[4] = {vv.x, vv.y, vv.z, vv.w};
#pragma unroll
            for (int i = 0; i < 4; i++)
#pragma unroll
                for (int j = 0; j < 4; j++)
                    acc[i][j] = fmaf(pa[i], vb[j], acc[i][j]);
        }
        __syncthreads();
    }

#pragma unroll
    for (int i = 0; i < 4; i++) {
        const float inv = 1.0f / l_i[i];
        const int s = qt * 64 + r0 + i;
        float* dst = g_ctx + (size_t)(s * BATCH + b) * HID + h * HDIM + c0;
        *(float4*)dst = make_float4(acc[i][0] * inv, acc[i][1] * inv,
                                    acc[i][2] * inv, acc[i][3] * inv);
    }
}

// ---------------------------------------------------------------------------
// Launch
// ---------------------------------------------------------------------------
extern "C" void kernel_launch(void* const* d_in, const int* in_sizes, int n_in,
                              void* d_out, int out_size) {
    const float* hs      = (const float*)d_in[0];
    const void*  mask    = d_in[1];
    const float* W_qkv   = (const float*)d_in[2];
    const float* b_qkv   = (const float*)d_in[3];
    const float* W_dense = (const float*)d_in[4];
    const float* b_dense = (const float*)d_in[5];
    float* out = (float*)d_out;

    float *mixed, *ctx;
    __nv_bfloat16 *pAh, *pAl, *pWqh, *pWql, *pWdh, *pWdl;
    cudaGetSymbolAddress((void**)&mixed, g_mixed);
    cudaGetSymbolAddress((void**)&ctx, g_ctx);
    cudaGetSymbolAddress((void**)&pAh, g_pA_hi);
    cudaGetSymbolAddress((void**)&pAl, g_pA_lo);
    cudaGetSymbolAddress((void**)&pWqh, g_pWq_hi);
    cudaGetSymbolAddress((void**)&pWql, g_pWq_lo);
    cudaGetSymbolAddress((void**)&pWdh, g_pWd_hi);
    cudaGetSymbolAddress((void**)&pWdl, g_pWd_lo);

    cudaFuncSetAttribute(gemm_mma, cudaFuncAttributeMaxDynamicSharedMemorySize, GT_SMEM);

    // 0) mask dtype
    detect_mask_dtype<<<1, 1>>>((const int*)mask);

    // 1) pack inputs for QKV GEMM
    pack_hilo<<<(M_ROWS * HID / 4) / 256, 256>>>(hs, pAh, pAl);
    pack_hilo<<<(QKV_N * HID / 4) / 256, 256>>>(W_qkv, pWqh, pWql);

    // 2) QKV GEMM (HMMA): [8192,1024] x [3072,1024]^T -> mixed
    gemm_mma<<<dim3(QKV_N / 128, M_ROWS / 128), 256, GT_SMEM>>>(
        pAh, pAl, pWqh, pWql, b_qkv, mixed, QKV_N);

    // 3) Flash attention -> ctx
    {
        const int smem_bytes = (64 * 64 * 3 + 64 * PS_STRIDE) * sizeof(float);
        cudaFuncSetAttribute(attention_kernel,
                             cudaFuncAttributeMaxDynamicSharedMemorySize, smem_bytes);
        dim3 grid(S_LEN / 64, BATCH * NHEADS);
        attention_kernel<<<grid, 256, smem_bytes>>>(mask, ctx);
    }

    // 4) pack ctx + W_dense, dense GEMM -> out
    pack_hilo<<<(M_ROWS * HID / 4) / 256, 256>>>(ctx, pAh, pAl);
    pack_hilo<<<(HID * HID / 4) / 256, 256>>>(W_dense, pWdh, pWdl);
    gemm_mma<<<dim3(HID / 128, M_ROWS / 128), 256, GT_SMEM>>>(
        pAh, pAl, pWdh, pWdl, b_dense, out, HID);
}

// round 8
// speedup vs baseline: 7.2795x; 1.8473x over previous
#include <cuda_runtime.h>
#include <cuda_bf16.h>
#include <math.h>
#include <stdint.h>

#define S_LEN 2048
#define BATCH 4
#define HID 1024
#define NHEADS 16
#define HDIM 64
#define M_ROWS (S_LEN * BATCH)   // 8192
#define QKV_N (3 * HID)          // 3072
#define GK HID                   // K dim of both GEMMs = 1024
#define MASK_VAL (-10000.0f)

// ---------------- scratch (allocation-free: device globals) ----------------
__device__ int g_mask_is_i32;
__device__ unsigned char g_mask_u8[(size_t)BATCH * S_LEN * S_LEN];   // 16.7 MB

// Q/K/V bf16 hi/lo, layout [bh=b*16+h][token][64]
#define QKV_ELEMS ((size_t)64 * S_LEN * HDIM)
__device__ __align__(16) __nv_bfloat16 g_Qh[QKV_ELEMS], g_Ql[QKV_ELEMS];
__device__ __align__(16) __nv_bfloat16 g_Kh[QKV_ELEMS], g_Kl[QKV_ELEMS];
__device__ __align__(16) __nv_bfloat16 g_Vh[QKV_ELEMS], g_Vl[QKV_ELEMS];

// A-operand packs (hs for QKV GEMM; later overwritten with ctx for dense GEMM)
__device__ __align__(16) __nv_bfloat16 g_pA_hi[(size_t)M_ROWS * HID];
__device__ __align__(16) __nv_bfloat16 g_pA_lo[(size_t)M_ROWS * HID];
__device__ __align__(16) __nv_bfloat16 g_pWq_hi[(size_t)QKV_N * HID];
__device__ __align__(16) __nv_bfloat16 g_pWq_lo[(size_t)QKV_N * HID];
__device__ __align__(16) __nv_bfloat16 g_pWd_hi[(size_t)HID * HID];
__device__ __align__(16) __nv_bfloat16 g_pWd_lo[(size_t)HID * HID];

// ---------------- helpers ----------------
__device__ __forceinline__ uint32_t smem_to_u32(const void* p) {
    uint32_t a;
    asm("{ .reg .u64 t; cvta.to.shared.u64 t, %1; cvt.u32.u64 %0, t; }" : "=r"(a) : "l"(p));
    return a;
}
__device__ __forceinline__ void cp_async16(uint32_t dst, const void* src) {
    asm volatile("cp.async.cg.shared.global [%0], [%1], 16;" :: "r"(dst), "l"(src));
}
#define CP_COMMIT() asm volatile("cp.async.commit_group;" ::: "memory")
#define CP_WAIT0()  asm volatile("cp.async.wait_group 0;" ::: "memory")
#define CP_WAIT1()  asm volatile("cp.async.wait_group 1;" ::: "memory")

__device__ __forceinline__ void ldmx4(uint32_t* r, uint32_t addr) {
    asm volatile("ldmatrix.sync.aligned.m8n8.x4.shared.b16 {%0,%1,%2,%3}, [%4];"
                 : "=r"(r[0]), "=r"(r[1]), "=r"(r[2]), "=r"(r[3]) : "r"(addr));
}
__device__ __forceinline__ void ldmx4t(uint32_t* r, uint32_t addr) {
    asm volatile("ldmatrix.sync.aligned.m8n8.x4.trans.shared.b16 {%0,%1,%2,%3}, [%4];"
                 : "=r"(r[0]), "=r"(r[1]), "=r"(r[2]), "=r"(r[3]) : "r"(addr));
}
__device__ __forceinline__ void mma16816(float* c, const uint32_t* a, uint32_t b0, uint32_t b1) {
    asm volatile(
        "mma.sync.aligned.m16n8k16.row.col.f32.bf16.bf16.f32 "
        "{%0,%1,%2,%3}, {%4,%5,%6,%7}, {%8,%9}, {%0,%1,%2,%3};"
        : "+f"(c[0]), "+f"(c[1]), "+f"(c[2]), "+f"(c[3])
        : "r"(a[0]), "r"(a[1]), "r"(a[2]), "r"(a[3]), "r"(b0), "r"(b1));
}
// pack two fp32 -> bf16x2 (vlow in bits 0:15)
__device__ __forceinline__ uint32_t packbf2(float vhigh, float vlow) {
    uint32_t r;
    asm("cvt.rn.bf16x2.f32 %0, %1, %2;" : "=r"(r) : "f"(vhigh), "f"(vlow));
    return r;
}
// hi/lo split of a fp32 pair -> two bf16x2 words
__device__ __forceinline__ void split_hilo(float v0, float v1, uint32_t& hi, uint32_t& lo) {
    hi = packbf2(v1, v0);
    const float h0 = __int_as_float(hi << 16);
    const float h1 = __int_as_float(hi & 0xFFFF0000u);
    lo = packbf2(v1 - h1, v0 - h0);
}
// fast exp on FMA pipe (x <= 0 typically; safe for very negative x)
__device__ __forceinline__ float fexp(float x) {
    float t = fmaxf(x * 1.4426950408889634f, -126.0f);
    float n = rintf(t);
    float f = t - n;
    float r = 0.0013333558f;
    r = fmaf(r, f, 0.0096181291f);
    r = fmaf(r, f, 0.0555041087f);
    r = fmaf(r, f, 0.2402265070f);
    r = fmaf(r, f, 0.6931471806f);
    r = fmaf(r, f, 1.0f);
    return r * __int_as_float(((int)n + 127) << 23);
}

// ---------------------------------------------------------------------------
// Mask dtype detect (parallel, no serial early-exit) + byte conversion
// ---------------------------------------------------------------------------
__global__ void detect_mask_dtype(const int* __restrict__ m) {
    int bad = 0;
#pragma unroll
    for (int i = 0; i < 32; i++) {
        unsigned v = (unsigned)m[threadIdx.x * 32 + i];
        bad |= (v > 1u);
    }
    unsigned any = __ballot_sync(0xFFFFFFFFu, bad);
    if (threadIdx.x == 0) g_mask_is_i32 = (any == 0) ? 1 : 0;
}

__global__ void __launch_bounds__(256)
convert_mask(const void* __restrict__ raw, unsigned char* __restrict__ out) {
    const size_t i = (size_t)blockIdx.x * 256 + threadIdx.x;   // per 4 output bytes
    uchar4 o;
    if (g_mask_is_i32) {
        const int4 v = ((const int4*)raw)[i];
        o = make_uchar4((unsigned char)v.x, (unsigned char)v.y,
                        (unsigned char)v.z, (unsigned char)v.w);
    } else {
        o = ((const uchar4*)raw)[i];
    }
    ((uchar4*)out)[i] = o;
}

// ---------------------------------------------------------------------------
// Pack fp32 -> hi/lo bf16 (row-major flat)
// ---------------------------------------------------------------------------
__global__ void __launch_bounds__(256)
pack_hilo(const float* __restrict__ src, __nv_bfloat16* __restrict__ hi,
          __nv_bfloat16* __restrict__ lo) {
    const size_t idx = (size_t)blockIdx.x * 256 + threadIdx.x;
    const float4 v = *(const float4*)(src + idx * 4);
    uint32_t h0, l0, h1, l1;
    split_hilo(v.x, v.y, h0, l0);
    split_hilo(v.z, v.w, h1, l1);
    *(uint2*)(hi + idx * 4) = make_uint2(h0, h1);
    *(uint2*)(lo + idx * 4) = make_uint2(l0, l1);
}

// ---------------------------------------------------------------------------
// bf16 hi/lo GEMM via mma.sync. epi_mode 0: fp32 C+bias. epi_mode 1: split
// QKV writer -> g_Q/K/V hi/lo [bh][token][64].
// ---------------------------------------------------------------------------
#define GP 80
#define GT_TILE (128 * GP)
#define GT_STAGE (4 * GT_TILE)
#define GT_SMEM (2 * GT_STAGE)

__global__ void __launch_bounds__(256)
gemm_mma(const __nv_bfloat16* __restrict__ Ahi, const __nv_bfloat16* __restrict__ Alo,
         const __nv_bfloat16* __restrict__ Bhi, const __nv_bfloat16* __restrict__ Blo,
         const float* __restrict__ bias, float* __restrict__ C, int n_dim, int epi_mode,
         __nv_bfloat16* qh, __nv_bfloat16* ql, __nv_bfloat16* kh,
         __nv_bfloat16* kl, __nv_bfloat16* vh, __nv_bfloat16* vl) {
    extern __shared__ __align__(1024) char smem[];
    const uint32_t sb = smem_to_u32(smem);
    const int tid = threadIdx.x;
    const int bx = blockIdx.x, by = blockIdx.y;
    const int w = tid >> 5, l = tid & 31;
    const int wm = w >> 1, wn = w & 1;

    const int c0row = tid >> 2,        c0col = tid & 3;
    const int c1row = (tid + 256) >> 2, c1col = (tid + 256) & 3;

    const __nv_bfloat16* srcs[4] = {Ahi, Alo, Bhi, Blo};
    const size_t rowbase[4] = {(size_t)by * 128, (size_t)by * 128,
                               (size_t)bx * 128, (size_t)bx * 128};

    float acc[2][8][4];
#pragma unroll
    for (int i = 0; i < 2; i++)
#pragma unroll
        for (int j = 0; j < 8; j++)
#pragma unroll
            for (int q = 0; q < 4; q++) acc[i][j][q] = 0.0f;

    const uint32_t a_lane = (uint32_t)(l & 15) * GP + ((l >> 4) & 1) * 16;
    const uint32_t b_lane = (uint32_t)((l & 7) + ((l >> 4) & 1) * 8) * GP + ((l >> 3) & 1) * 16;

    auto issue = [&](int s, int k0) {
        const uint32_t st = sb + s * GT_STAGE;
#pragma unroll
        for (int t = 0; t < 4; t++) {
            const __nv_bfloat16* base = srcs[t] + (rowbase[t]) * GK + k0;
            cp_async16(st + t * GT_TILE + c0row * GP + c0col * 16,
                       base + (size_t)c0row * GK + c0col * 8);
            cp_async16(st + t * GT_TILE + c1row * GP + c1col * 16,
                       base + (size_t)c1row * GK + c1col * 8);
        }
        CP_COMMIT();
    };

    issue(0, 0);

    for (int kt = 0; kt < GK / 32; kt++) {
        const int s = kt & 1;
        CP_WAIT0();
        __syncthreads();
        if (kt + 1 < GK / 32) issue(s ^ 1, (kt + 1) * 32);

        const uint32_t st = sb + s * GT_STAGE;
#pragma unroll
        for (int ks = 0; ks < 2; ks++) {
            const uint32_t kb = ks * 32;
            uint32_t ah[2][4], al[2][4], bh2[4][4], bl2[4][4];
#pragma unroll
            for (int mi = 0; mi < 2; mi++) {
                const uint32_t ao = (uint32_t)(wm * 32 + mi * 16) * GP + kb + a_lane;
                ldmx4(ah[mi], st + ao);
                ldmx4(al[mi], st + GT_TILE + ao);
            }
#pragma unroll
            for (int bi = 0; bi < 4; bi++) {
                const uint32_t bo = (uint32_t)(wn * 64 + bi * 16) * GP + kb + b_lane;
                ldmx4(bh2[bi], st + 2 * GT_TILE + bo);
                ldmx4(bl2[bi], st + 3 * GT_TILE + bo);
            }
#pragma unroll
            for (int mi = 0; mi < 2; mi++)
#pragma unroll
                for (int bi = 0; bi < 4; bi++)
#pragma unroll
                    for (int t = 0; t < 2; t++) {
                        float* c = acc[mi][bi * 2 + t];
                        mma16816(c, ah[mi], bh2[bi][t * 2], bh2[bi][t * 2 + 1]);
                        mma16816(c, al[mi], bh2[bi][t * 2], bh2[bi][t * 2 + 1]);
                        mma16816(c, ah[mi], bl2[bi][t * 2], bl2[bi][t * 2 + 1]);
                    }
        }
        __syncthreads();
    }

    const int mg = by * 128 + wm * 32 + (l >> 2);
    const int ng0 = bx * 128 + wn * 64 + (l & 3) * 2;

    if (epi_mode == 0) {
#pragma unroll
        for (int mi = 0; mi < 2; mi++) {
#pragma unroll
            for (int ni = 0; ni < 8; ni++) {
                const int n = ng0 + ni * 8;
                const float2 bv = *(const float2*)(bias + n);
                const int m0 = mg + mi * 16;
                *(float2*)(C + (size_t)m0 * n_dim + n) =
                    make_float2(acc[mi][ni][0] + bv.x, acc[mi][ni][1] + bv.y);
                *(float2*)(C + (size_t)(m0 + 8) * n_dim + n) =
                    make_float2(acc[mi][ni][2] + bv.x, acc[mi][ni][3] + bv.y);
            }
        }
    } else {
        // QKV split epilogue: n -> (h, kind, d); m -> (s, b)
#pragma unroll
        for (int mi = 0; mi < 2; mi++) {
#pragma unroll
            for (int ni = 0; ni < 8; ni++) {
                const int n = ng0 + ni * 8;
                const int hh = n / 192;
                const int r = n - hh * 192;
                const int kind = r >> 6;
                const int d = r & 63;
                const float b0 = bias[n], b1 = bias[n + 1];
                __nv_bfloat16* dsth = (kind == 0) ? qh : (kind == 1) ? kh : vh;
                __nv_bfloat16* dstl = (kind == 0) ? ql : (kind == 1) ? kl : vl;
#pragma unroll
                for (int hf = 0; hf < 2; hf++) {
                    const int m = mg + mi * 16 + hf * 8;
                    const int s = m >> 2, bb = m & 3;
                    const size_t off = ((size_t)(bb * NHEADS + hh) * S_LEN + s) * 64 + d;
                    uint32_t hiw, low;
                    split_hilo(acc[mi][ni][hf * 2 + 0] + b0,
                               acc[mi][ni][hf * 2 + 1] + b1, hiw, low);
                    *(uint32_t*)(dsth + off) = hiw;
                    *(uint32_t*)(dstl + off) = low;
                }
            }
        }
    }
}

// ---------------------------------------------------------------------------
// Tensor-core flash attention. Grid (16 qtiles, 64 bh), 256 threads (8 warps).
// Warp w: q rows [w*16, w*16+16). K-tiles of 128 tokens, double-buffered.
// smem/stage: Kh,Kl,Vh,Vl [128 x pitch72 bf16] + mask bytes [128x128].
// ---------------------------------------------------------------------------
#define APT 72                      // K/V smem pitch in bf16 elems (144 B)
#define A_ARR (128 * APT * 2)       // 18432 B per array
#define A_MASK_OFF (4 * A_ARR)      // 73728
#define A_STAGE (A_MASK_OFF + 128 * 128)  // 90112
#define A_SMEM (2 * A_STAGE)        // 180224

__global__ void __launch_bounds__(256)
attention_mma(const unsigned char* __restrict__ maskb,
              const __nv_bfloat16* __restrict__ Qh, const __nv_bfloat16* __restrict__ Ql,
              const __nv_bfloat16* __restrict__ Kh, const __nv_bfloat16* __restrict__ Kl,
              const __nv_bfloat16* __restrict__ Vh, const __nv_bfloat16* __restrict__ Vl,
              __nv_bfloat16* __restrict__ ctxh, __nv_bfloat16* __restrict__ ctxl) {
    extern __shared__ __align__(1024) char smem[];
    const uint32_t sb = smem_to_u32(smem);
    const int tid = threadIdx.x, w = tid >> 5, l = tid & 31;
    const int qt = blockIdx.x, bh = blockIdx.y;
    const int b = bh >> 4, h = bh & 15;
    const int q0 = qt * 128;

    // Q fragments straight from gmem (fragment-layout addressed)
    uint32_t qfh[4][4], qfl[4][4];
    {
        const __nv_bfloat16* qgh = Qh + ((size_t)bh * S_LEN + q0 + w * 16) * 64;
        const __nv_bfloat16* qgl = Ql + ((size_t)bh * S_LEN + q0 + w * 16) * 64;
        const int r0 = l >> 2, k0 = 2 * (l & 3);
#pragma unroll
        for (int ks = 0; ks < 4; ks++) {
            const int kk = ks * 16 + k0;
            qfh[ks][0] = *(const uint32_t*)(qgh + r0 * 64 + kk);
            qfh[ks][1] = *(const uint32_t*)(qgh + (r0 + 8) * 64 + kk);
            qfh[ks][2] = *(const uint32_t*)(qgh + r0 * 64 + kk + 8);
            qfh[ks][3] = *(const uint32_t*)(qgh + (r0 + 8) * 64 + kk + 8);
            qfl[ks][0] = *(const uint32_t*)(qgl + r0 * 64 + kk);
            qfl[ks][1] = *(const uint32_t*)(qgl + (r0 + 8) * 64 + kk);
            qfl[ks][2] = *(const uint32_t*)(qgl + r0 * 64 + kk + 8);
            qfl[ks][3] = *(const uint32_t*)(qgl + (r0 + 8) * 64 + kk + 8);
        }
    }

    float acc[8][4];
#pragma unroll
    for (int i = 0; i < 8; i++)
#pragma unroll
        for (int j = 0; j < 4; j++) acc[i][j] = 0.0f;
    float m0 = -1e30f, m1 = -1e30f, lsum0 = 0.0f, lsum1 = 0.0f;

    auto issue = [&](int kt) {
        const uint32_t st = sb + (kt & 1) * A_STAGE;
        const __nv_bfloat16* arrs[4] = {Kh, Kl, Vh, Vl};
#pragma unroll
        for (int i = 0; i < 16; i++) {
            const int c = tid + i * 256;
            const int arr = c >> 10;
            const int cc = c & 1023;
            const int row = cc >> 3, col = cc & 7;
            cp_async16(st + arr * A_ARR + row * 144 + col * 16,
                       arrs[arr] + ((size_t)bh * S_LEN + kt * 128 + row) * 64 + col * 8);
        }
#pragma unroll
        for (int i = 0; i < 4; i++) {
            const int c = tid + i * 256;
            const int row = c >> 3, col = (c & 7) * 16;
            cp_async16(st + A_MASK_OFF + row * 128 + col,
                       maskb + ((size_t)b * S_LEN + q0 + row) * S_LEN + kt * 128 + col);
        }
        CP_COMMIT();
    };

    issue(0);

    const uint32_t klane = (uint32_t)((l & 7) + ((l >> 4) & 1) * 8) * 144 + ((l >> 3) & 1) * 16;
    const uint32_t vlane = (uint32_t)((l & 7) + ((l >> 3) & 1) * 8) * 144 + ((l >> 4) & 1) * 16;
    const int mrow = w * 16 + (l >> 2);
    const int mcol = 2 * (l & 3);

    for (int kt = 0; kt < 16; kt++) {
        if (kt + 1 < 16) { issue(kt + 1); CP_WAIT1(); } else { CP_WAIT0(); }
        __syncthreads();
        const uint32_t st = sb + (kt & 1) * A_STAGE;

        // ---- scores = Q K^T (hi/lo, 3 terms) ----
        float sc[16][4];
#pragma unroll
        for (int i = 0; i < 16; i++) { sc[i][0] = sc[i][1] = sc[i][2] = sc[i][3] = 0.0f; }
#pragma unroll
        for (int ks = 0; ks < 4; ks++) {
#pragma unroll
            for (int nt2 = 0; nt2 < 8; nt2++) {
                uint32_t kh4[4], kl4[4];
                const uint32_t ao = st + (uint32_t)(nt2 * 16) * 144 + ks * 32 + klane;
                ldmx4(kh4, ao);
                ldmx4(kl4, ao + A_ARR);
                mma16816(sc[2 * nt2],     qfh[ks], kh4[0], kh4[1]);
                mma16816(sc[2 * nt2],     qfl[ks], kh4[0], kh4[1]);
                mma16816(sc[2 * nt2],     qfh[ks], kl4[0], kl4[1]);
                mma16816(sc[2 * nt2 + 1], qfh[ks], kh4[2], kh4[3]);
                mma16816(sc[2 * nt2 + 1], qfl[ks], kh4[2], kh4[3]);
                mma16816(sc[2 * nt2 + 1], qfh[ks], kl4[2], kl4[3]);
            }
        }

        // ---- scale + mask (byte tile in smem) ----
#pragma unroll
        for (int nt = 0; nt < 16; nt++) {
            const uint32_t a0 = st + A_MASK_OFF + mrow * 128 + nt * 8 + mcol;
            unsigned short mm0, mm1;
            asm volatile("ld.shared.u16 %0, [%1];" : "=h"(mm0) : "r"(a0));
            asm volatile("ld.shared.u16 %0, [%1];" : "=h"(mm1) : "r"(a0 + 8 * 128));
            sc[nt][0] = (mm0 & 0xFF) ? MASK_VAL : sc[nt][0] * 0.125f;
            sc[nt][1] = (mm0 >> 8)   ? MASK_VAL : sc[nt][1] * 0.125f;
            sc[nt][2] = (mm1 & 0xFF) ? MASK_VAL : sc[nt][2] * 0.125f;
            sc[nt][3] = (mm1 >> 8)   ? MASK_VAL : sc[nt][3] * 0.125f;
        }

        // ---- online softmax (rows l/4 and l/4+8; quad = lanes xor 1,2) ----
        float mx0 = sc[0][0], mx1 = sc[0][2];
#pragma unroll
        for (int nt = 0; nt < 16; nt++) {
            mx0 = fmaxf(mx0, fmaxf(sc[nt][0], sc[nt][1]));
            mx1 = fmaxf(mx1, fmaxf(sc[nt][2], sc[nt][3]));
        }
        mx0 = fmaxf(mx0, __shfl_xor_sync(0xFFFFFFFFu, mx0, 1));
        mx0 = fmaxf(mx0, __shfl_xor_sync(0xFFFFFFFFu, mx0, 2));
        mx1 = fmaxf(mx1, __shfl_xor_sync(0xFFFFFFFFu, mx1, 1));
        mx1 = fmaxf(mx1, __shfl_xor_sync(0xFFFFFFFFu, mx1, 2));

        const float nm0 = fmaxf(m0, mx0), nm1 = fmaxf(m1, mx1);
        const float cr0 = fexp(m0 - nm0), cr1 = fexp(m1 - nm1);
        m0 = nm0; m1 = nm1;

        float s0 = 0.0f, s1 = 0.0f;
#pragma unroll
        for (int nt = 0; nt < 16; nt++) {
            sc[nt][0] = fexp(sc[nt][0] - nm0); s0 += sc[nt][0];
            sc[nt][1] = fexp(sc[nt][1] - nm0); s0 += sc[nt][1];
            sc[nt][2] = fexp(sc[nt][2] - nm1); s1 += sc[nt][2];
            sc[nt][3] = fexp(sc[nt][3] - nm1); s1 += sc[nt][3];
        }
        s0 += __shfl_xor_sync(0xFFFFFFFFu, s0, 1);
        s0 += __shfl_xor_sync(0xFFFFFFFFu, s0, 2);
        s1 += __shfl_xor_sync(0xFFFFFFFFu, s1, 1);
        s1 += __shfl_xor_sync(0xFFFFFFFFu, s1, 2);
        lsum0 = lsum0 * cr0 + s0;
        lsum1 = lsum1 * cr1 + s1;
#pragma unroll
        for (int nt = 0; nt < 8; nt++) {
            acc[nt][0] *= cr0; acc[nt][1] *= cr0;
            acc[nt][2] *= cr1; acc[nt][3] *= cr1;
        }

        // ---- ctx += P V (P from score frags, hi/lo; V via ldmatrix.trans) ----
#pragma unroll
        for (int kt16 = 0; kt16 < 8; kt16++) {
            uint32_t ph[4], pl[4];
            split_hilo(sc[2 * kt16][0],     sc[2 * kt16][1],     ph[0], pl[0]);
            split_hilo(sc[2 * kt16][2],     sc[2 * kt16][3],     ph[1], pl[1]);
            split_hilo(sc[2 * kt16 + 1][0], sc[2 * kt16 + 1][1], ph[2], pl[2]);
            split_hilo(sc[2 * kt16 + 1][2], sc[2 * kt16 + 1][3], ph[3], pl[3]);
#pragma unroll
            for (int db = 0; db < 4; db++) {
                uint32_t vh4[4], vl4[4];
                const uint32_t ao = st + 2 * A_ARR + (uint32_t)(kt16 * 16) * 144 + db * 32 + vlane;
                ldmx4t(vh4, ao);
                ldmx4t(vl4, ao + A_ARR);
                mma16816(acc[2 * db],     ph, vh4[0], vh4[1]);
                mma16816(acc[2 * db],     pl, vh4[0], vh4[1]);
                mma16816(acc[2 * db],     ph, vl4[0], vl4[1]);
                mma16816(acc[2 * db + 1], ph, vh4[2], vh4[3]);
                mma16816(acc[2 * db + 1], pl, vh4[2], vh4[3]);
                mma16816(acc[2 * db + 1], ph, vl4[2], vl4[3]);
            }
        }
        __syncthreads();
    }

    // ---- normalize + write ctx as bf16 hi/lo (dense GEMM A operand) ----
    const float i0 = 1.0f / lsum0, i1 = 1.0f / lsum1;
    const int srow = q0 + w * 16 + (l >> 2);
    const int colb = h * 64 + 2 * (l & 3);
#pragma unroll
    for (int nt = 0; nt < 8; nt++) {
        const int col = colb + nt * 8;
        uint32_t hiw, low;
        split_hilo(acc[nt][0] * i0, acc[nt][1] * i0, hiw, low);
        const size_t off0 = ((size_t)srow * 4 + b) * HID + col;
        *(uint32_t*)(ctxh + off0) = hiw;
        *(uint32_t*)(ctxl + off0) = low;
        split_hilo(acc[nt][2] * i1, acc[nt][3] * i1, hiw, low);
        const size_t off1 = ((size_t)(srow + 8) * 4 + b) * HID + col;
        *(uint32_t*)(ctxh + off1) = hiw;
        *(uint32_t*)(ctxl + off1) = low;
    }
}

// ---------------------------------------------------------------------------
// Launch
// ---------------------------------------------------------------------------
extern "C" void kernel_launch(void* const* d_in, const int* in_sizes, int n_in,
                              void* d_out, int out_size) {
    const float* hs      = (const float*)d_in[0];
    const void*  mask    = d_in[1];
    const float* W_qkv   = (const float*)d_in[2];
    const float* b_qkv   = (const float*)d_in[3];
    const float* W_dense = (const float*)d_in[4];
    const float* b_dense = (const float*)d_in[5];
    float* out = (float*)d_out;

    __nv_bfloat16 *pAh, *pAl, *pWqh, *pWql, *pWdh, *pWdl;
    __nv_bfloat16 *Qh, *Ql, *Kh, *Kl, *Vh, *Vl;
    unsigned char* masku8;
    cudaGetSymbolAddress((void**)&pAh, g_pA_hi);
    cudaGetSymbolAddress((void**)&pAl, g_pA_lo);
    cudaGetSymbolAddress((void**)&pWqh, g_pWq_hi);
    cudaGetSymbolAddress((void**)&pWql, g_pWq_lo);
    cudaGetSymbolAddress((void**)&pWdh, g_pWd_hi);
    cudaGetSymbolAddress((void**)&pWdl, g_pWd_lo);
    cudaGetSymbolAddress((void**)&Qh, g_Qh);
    cudaGetSymbolAddress((void**)&Ql, g_Ql);
    cudaGetSymbolAddress((void**)&Kh, g_Kh);
    cudaGetSymbolAddress((void**)&Kl, g_Kl);
    cudaGetSymbolAddress((void**)&Vh, g_Vh);
    cudaGetSymbolAddress((void**)&Vl, g_Vl);
    cudaGetSymbolAddress((void**)&masku8, g_mask_u8);

    cudaFuncSetAttribute(gemm_mma, cudaFuncAttributeMaxDynamicSharedMemorySize, GT_SMEM);
    cudaFuncSetAttribute(attention_mma, cudaFuncAttributeMaxDynamicSharedMemorySize, A_SMEM);

    // 0) mask dtype + byte conversion
    detect_mask_dtype<<<1, 32>>>((const int*)mask);
    convert_mask<<<(BATCH * S_LEN * S_LEN / 4) / 256, 256>>>(mask, masku8);

    // 1) pack hs + W_qkv
    pack_hilo<<<(M_ROWS * HID / 4) / 256, 256>>>(hs, pAh, pAl);
    pack_hilo<<<(QKV_N * HID / 4) / 256, 256>>>(W_qkv, pWqh, pWql);

    // 2) QKV GEMM -> split bf16 hi/lo Q/K/V
    gemm_mma<<<dim3(QKV_N / 128, M_ROWS / 128), 256, GT_SMEM>>>(
        pAh, pAl, pWqh, pWql, b_qkv, nullptr, QKV_N, 1, Qh, Ql, Kh, Kl, Vh, Vl);

    // 3) tensor-core flash attention -> ctx hi/lo (into pA buffers)
    attention_mma<<<dim3(S_LEN / 128, BATCH * NHEADS), 256, A_SMEM>>>(
        masku8, Qh, Ql, Kh, Kl, Vh, Vl, pAh, pAl);

    // 4) pack W_dense + dense GEMM -> out
    pack_hilo<<<(HID * HID / 4) / 256, 256>>>(W_dense, pWdh, pWdl);
    gemm_mma<<<dim3(HID / 128, M_ROWS / 128), 256, GT_SMEM>>>(
        pAh, pAl, pWdh, pWdl, b_dense, out, HID, 0,
        nullptr, nullptr, nullptr, nullptr, nullptr, nullptr);
}

// round 9
// speedup vs baseline: 7.7176x; 1.0602x over previous
#include <cuda_runtime.h>
#include <cuda_bf16.h>
#include <math.h>
#include <stdint.h>

#define S_LEN 2048
#define BATCH 4
#define HID 1024
#define NHEADS 16
#define HDIM 64
#define M_ROWS (S_LEN * BATCH)   // 8192
#define QKV_N (3 * HID)          // 3072
#define GK HID                   // K dim of both GEMMs = 1024
#define MASK_VAL (-10000.0f)

// ---------------- scratch (allocation-free: device globals) ----------------
__device__ int g_mask_is_i32;
__device__ unsigned char g_mask_u8[(size_t)BATCH * S_LEN * S_LEN];   // 16.7 MB

// Q/K/V bf16 hi/lo, layout [bh=b*16+h][token][64]
#define QKV_ELEMS ((size_t)64 * S_LEN * HDIM)
__device__ __align__(16) __nv_bfloat16 g_Qh[QKV_ELEMS], g_Ql[QKV_ELEMS];
__device__ __align__(16) __nv_bfloat16 g_Kh[QKV_ELEMS], g_Kl[QKV_ELEMS];
__device__ __align__(16) __nv_bfloat16 g_Vh[QKV_ELEMS], g_Vl[QKV_ELEMS];

// A-operand packs (hs for QKV GEMM; later overwritten with ctx for dense GEMM)
__device__ __align__(16) __nv_bfloat16 g_pA_hi[(size_t)M_ROWS * HID];
__device__ __align__(16) __nv_bfloat16 g_pA_lo[(size_t)M_ROWS * HID];
__device__ __align__(16) __nv_bfloat16 g_pWq_hi[(size_t)QKV_N * HID];
__device__ __align__(16) __nv_bfloat16 g_pWq_lo[(size_t)QKV_N * HID];
__device__ __align__(16) __nv_bfloat16 g_pWd_hi[(size_t)HID * HID];
__device__ __align__(16) __nv_bfloat16 g_pWd_lo[(size_t)HID * HID];

// ---------------- helpers ----------------
__device__ __forceinline__ uint32_t smem_to_u32(const void* p) {
    uint32_t a;
    asm("{ .reg .u64 t; cvta.to.shared.u64 t, %1; cvt.u32.u64 %0, t; }" : "=r"(a) : "l"(p));
    return a;
}
__device__ __forceinline__ void cp_async16(uint32_t dst, const void* src) {
    asm volatile("cp.async.cg.shared.global [%0], [%1], 16;" :: "r"(dst), "l"(src));
}
#define CP_COMMIT() asm volatile("cp.async.commit_group;" ::: "memory")
#define CP_WAIT0()  asm volatile("cp.async.wait_group 0;" ::: "memory")
#define CP_WAIT1()  asm volatile("cp.async.wait_group 1;" ::: "memory")

__device__ __forceinline__ void ldmx4(uint32_t* r, uint32_t addr) {
    asm volatile("ldmatrix.sync.aligned.m8n8.x4.shared.b16 {%0,%1,%2,%3}, [%4];"
                 : "=r"(r[0]), "=r"(r[1]), "=r"(r[2]), "=r"(r[3]) : "r"(addr));
}
__device__ __forceinline__ void ldmx4t(uint32_t* r, uint32_t addr) {
    asm volatile("ldmatrix.sync.aligned.m8n8.x4.trans.shared.b16 {%0,%1,%2,%3}, [%4];"
                 : "=r"(r[0]), "=r"(r[1]), "=r"(r[2]), "=r"(r[3]) : "r"(addr));
}
__device__ __forceinline__ void mma16816(float* c, const uint32_t* a, uint32_t b0, uint32_t b1) {
    asm volatile(
        "mma.sync.aligned.m16n8k16.row.col.f32.bf16.bf16.f32 "
        "{%0,%1,%2,%3}, {%4,%5,%6,%7}, {%8,%9}, {%0,%1,%2,%3};"
        : "+f"(c[0]), "+f"(c[1]), "+f"(c[2]), "+f"(c[3])
        : "r"(a[0]), "r"(a[1]), "r"(a[2]), "r"(a[3]), "r"(b0), "r"(b1));
}
// pack two fp32 -> bf16x2 (vlow in bits 0:15)
__device__ __forceinline__ uint32_t packbf2(float vhigh, float vlow) {
    uint32_t r;
    asm("cvt.rn.bf16x2.f32 %0, %1, %2;" : "=r"(r) : "f"(vhigh), "f"(vlow));
    return r;
}
// hi/lo split of a fp32 pair -> two bf16x2 words
__device__ __forceinline__ void split_hilo(float v0, float v1, uint32_t& hi, uint32_t& lo) {
    hi = packbf2(v1, v0);
    const float h0 = __int_as_float(hi << 16);
    const float h1 = __int_as_float(hi & 0xFFFF0000u);
    lo = packbf2(v1 - h1, v0 - h0);
}
// fast exp on FMA pipe
__device__ __forceinline__ float fexp(float x) {
    float t = fmaxf(x * 1.4426950408889634f, -126.0f);
    float n = rintf(t);
    float f = t - n;
    float r = 0.0013333558f;
    r = fmaf(r, f, 0.0096181291f);
    r = fmaf(r, f, 0.0555041087f);
    r = fmaf(r, f, 0.2402265070f);
    r = fmaf(r, f, 0.6931471806f);
    r = fmaf(r, f, 1.0f);
    return r * __int_as_float(((int)n + 127) << 23);
}

// ---------------------------------------------------------------------------
// Mask dtype detect + byte conversion
// ---------------------------------------------------------------------------
__global__ void detect_mask_dtype(const int* __restrict__ m) {
    int bad = 0;
#pragma unroll
    for (int i = 0; i < 32; i++) {
        unsigned v = (unsigned)m[threadIdx.x * 32 + i];
        bad |= (v > 1u);
    }
    unsigned any = __ballot_sync(0xFFFFFFFFu, bad);
    if (threadIdx.x == 0) g_mask_is_i32 = (any == 0) ? 1 : 0;
}

__global__ void __launch_bounds__(256)
convert_mask(const void* __restrict__ raw, unsigned char* __restrict__ out) {
    const size_t i = (size_t)blockIdx.x * 256 + threadIdx.x;
    uchar4 o;
    if (g_mask_is_i32) {
        const int4 v = ((const int4*)raw)[i];
        o = make_uchar4((unsigned char)v.x, (unsigned char)v.y,
                        (unsigned char)v.z, (unsigned char)v.w);
    } else {
        o = ((const uchar4*)raw)[i];
    }
    ((uchar4*)out)[i] = o;
}

// ---------------------------------------------------------------------------
// Pack fp32 -> hi/lo bf16 (row-major flat)
// ---------------------------------------------------------------------------
__global__ void __launch_bounds__(256)
pack_hilo(const float* __restrict__ src, __nv_bfloat16* __restrict__ hi,
          __nv_bfloat16* __restrict__ lo) {
    const size_t idx = (size_t)blockIdx.x * 256 + threadIdx.x;
    const float4 v = *(const float4*)(src + idx * 4);
    uint32_t h0, l0, h1, l1;
    split_hilo(v.x, v.y, h0, l0);
    split_hilo(v.z, v.w, h1, l1);
    *(uint2*)(hi + idx * 4) = make_uint2(h0, h1);
    *(uint2*)(lo + idx * 4) = make_uint2(l0, l1);
}

// ---------------------------------------------------------------------------
// bf16 hi/lo GEMM via mma.sync (unchanged from R8 — 57.5% tensor)
// ---------------------------------------------------------------------------
#define GP 80
#define GT_TILE (128 * GP)
#define GT_STAGE (4 * GT_TILE)
#define GT_SMEM (2 * GT_STAGE)

__global__ void __launch_bounds__(256)
gemm_mma(const __nv_bfloat16* __restrict__ Ahi, const __nv_bfloat16* __restrict__ Alo,
         const __nv_bfloat16* __restrict__ Bhi, const __nv_bfloat16* __restrict__ Blo,
         const float* __restrict__ bias, float* __restrict__ C, int n_dim, int epi_mode,
         __nv_bfloat16* qh, __nv_bfloat16* ql, __nv_bfloat16* kh,
         __nv_bfloat16* kl, __nv_bfloat16* vh, __nv_bfloat16* vl) {
    extern __shared__ __align__(1024) char smem[];
    const uint32_t sb = smem_to_u32(smem);
    const int tid = threadIdx.x;
    const int bx = blockIdx.x, by = blockIdx.y;
    const int w = tid >> 5, l = tid & 31;
    const int wm = w >> 1, wn = w & 1;

    const int c0row = tid >> 2,        c0col = tid & 3;
    const int c1row = (tid + 256) >> 2, c1col = (tid + 256) & 3;

    const __nv_bfloat16* srcs[4] = {Ahi, Alo, Bhi, Blo};
    const size_t rowbase[4] = {(size_t)by * 128, (size_t)by * 128,
                               (size_t)bx * 128, (size_t)bx * 128};

    float acc[2][8][4];
#pragma unroll
    for (int i = 0; i < 2; i++)
#pragma unroll
        for (int j = 0; j < 8; j++)
#pragma unroll
            for (int q = 0; q < 4; q++) acc[i][j][q] = 0.0f;

    const uint32_t a_lane = (uint32_t)(l & 15) * GP + ((l >> 4) & 1) * 16;
    const uint32_t b_lane = (uint32_t)((l & 7) + ((l >> 4) & 1) * 8) * GP + ((l >> 3) & 1) * 16;

    auto issue = [&](int s, int k0) {
        const uint32_t st = sb + s * GT_STAGE;
#pragma unroll
        for (int t = 0; t < 4; t++) {
            const __nv_bfloat16* base = srcs[t] + (rowbase[t]) * GK + k0;
            cp_async16(st + t * GT_TILE + c0row * GP + c0col * 16,
                       base + (size_t)c0row * GK + c0col * 8);
            cp_async16(st + t * GT_TILE + c1row * GP + c1col * 16,
                       base + (size_t)c1row * GK + c1col * 8);
        }
        CP_COMMIT();
    };

    issue(0, 0);

    for (int kt = 0; kt < GK / 32; kt++) {
        const int s = kt & 1;
        CP_WAIT0();
        __syncthreads();
        if (kt + 1 < GK / 32) issue(s ^ 1, (kt + 1) * 32);

        const uint32_t st = sb + s * GT_STAGE;
#pragma unroll
        for (int ks = 0; ks < 2; ks++) {
            const uint32_t kb = ks * 32;
            uint32_t ah[2][4], al[2][4], bh2[4][4], bl2[4][4];
#pragma unroll
            for (int mi = 0; mi < 2; mi++) {
                const uint32_t ao = (uint32_t)(wm * 32 + mi * 16) * GP + kb + a_lane;
                ldmx4(ah[mi], st + ao);
                ldmx4(al[mi], st + GT_TILE + ao);
            }
#pragma unroll
            for (int bi = 0; bi < 4; bi++) {
                const uint32_t bo = (uint32_t)(wn * 64 + bi * 16) * GP + kb + b_lane;
                ldmx4(bh2[bi], st + 2 * GT_TILE + bo);
                ldmx4(bl2[bi], st + 3 * GT_TILE + bo);
            }
#pragma unroll
            for (int mi = 0; mi < 2; mi++)
#pragma unroll
                for (int bi = 0; bi < 4; bi++)
#pragma unroll
                    for (int t = 0; t < 2; t++) {
                        float* c = acc[mi][bi * 2 + t];
                        mma16816(c, ah[mi], bh2[bi][t * 2], bh2[bi][t * 2 + 1]);
                        mma16816(c, al[mi], bh2[bi][t * 2], bh2[bi][t * 2 + 1]);
                        mma16816(c, ah[mi], bl2[bi][t * 2], bl2[bi][t * 2 + 1]);
                    }
        }
        __syncthreads();
    }

    const int mg = by * 128 + wm * 32 + (l >> 2);
    const int ng0 = bx * 128 + wn * 64 + (l & 3) * 2;

    if (epi_mode == 0) {
#pragma unroll
        for (int mi = 0; mi < 2; mi++) {
#pragma unroll
            for (int ni = 0; ni < 8; ni++) {
                const int n = ng0 + ni * 8;
                const float2 bv = *(const float2*)(bias + n);
                const int m0 = mg + mi * 16;
                *(float2*)(C + (size_t)m0 * n_dim + n) =
                    make_float2(acc[mi][ni][0] + bv.x, acc[mi][ni][1] + bv.y);
                *(float2*)(C + (size_t)(m0 + 8) * n_dim + n) =
                    make_float2(acc[mi][ni][2] + bv.x, acc[mi][ni][3] + bv.y);
            }
        }
    } else {
#pragma unroll
        for (int mi = 0; mi < 2; mi++) {
#pragma unroll
            for (int ni = 0; ni < 8; ni++) {
                const int n = ng0 + ni * 8;
                const int hh = n / 192;
                const int r = n - hh * 192;
                const int kind = r >> 6;
                const int d = r & 63;
                const float b0 = bias[n], b1 = bias[n + 1];
                __nv_bfloat16* dsth = (kind == 0) ? qh : (kind == 1) ? kh : vh;
                __nv_bfloat16* dstl = (kind == 0) ? ql : (kind == 1) ? kl : vl;
#pragma unroll
                for (int hf = 0; hf < 2; hf++) {
                    const int m = mg + mi * 16 + hf * 8;
                    const int s = m >> 2, bb = m & 3;
                    const size_t off = ((size_t)(bb * NHEADS + hh) * S_LEN + s) * 64 + d;
                    uint32_t hiw, low;
                    split_hilo(acc[mi][ni][hf * 2 + 0] + b0,
                               acc[mi][ni][hf * 2 + 1] + b1, hiw, low);
                    *(uint32_t*)(dsth + off) = hiw;
                    *(uint32_t*)(dstl + off) = low;
                }
            }
        }
    }
}

// ---------------------------------------------------------------------------
// Tensor-core flash attention v2: K-tile 64 tokens, 2 CTAs/SM.
// Grid (16 qtiles, 64 bh), 256 threads (8 warps), warp w: q rows [w*16,+16).
// smem/stage: Kh,Kl,Vh,Vl [64 x pitch72 bf16] + mask bytes [128x64].
// ---------------------------------------------------------------------------
#define A_ARR (64 * 144)                  // 9216 B per array
#define A_MASK_OFF (4 * A_ARR)            // 36864
#define A_STAGE (A_MASK_OFF + 128 * 64)   // 45056
#define A_SMEM (2 * A_STAGE)              // 90112 -> 2 CTAs/SM

__global__ void __launch_bounds__(256, 2)
attention_mma(const unsigned char* __restrict__ maskb,
              const __nv_bfloat16* __restrict__ Qh, const __nv_bfloat16* __restrict__ Ql,
              const __nv_bfloat16* __restrict__ Kh, const __nv_bfloat16* __restrict__ Kl,
              const __nv_bfloat16* __restrict__ Vh, const __nv_bfloat16* __restrict__ Vl,
              __nv_bfloat16* __restrict__ ctxh, __nv_bfloat16* __restrict__ ctxl) {
    extern __shared__ __align__(1024) char smem[];
    const uint32_t sb = smem_to_u32(smem);
    const int tid = threadIdx.x, w = tid >> 5, l = tid & 31;
    const int qt = blockIdx.x, bh = blockIdx.y;
    const int b = bh >> 4, h = bh & 15;
    const int q0 = qt * 128;

    // Q fragments straight from gmem
    uint32_t qfh[4][4], qfl[4][4];
    {
        const __nv_bfloat16* qgh = Qh + ((size_t)bh * S_LEN + q0 + w * 16) * 64;
        const __nv_bfloat16* qgl = Ql + ((size_t)bh * S_LEN + q0 + w * 16) * 64;
        const int r0 = l >> 2, k0 = 2 * (l & 3);
#pragma unroll
        for (int ks = 0; ks < 4; ks++) {
            const int kk = ks * 16 + k0;
            qfh[ks][0] = *(const uint32_t*)(qgh + r0 * 64 + kk);
            qfh[ks][1] = *(const uint32_t*)(qgh + (r0 + 8) * 64 + kk);
            qfh[ks][2] = *(const uint32_t*)(qgh + r0 * 64 + kk + 8);
            qfh[ks][3] = *(const uint32_t*)(qgh + (r0 + 8) * 64 + kk + 8);
            qfl[ks][0] = *(const uint32_t*)(qgl + r0 * 64 + kk);
            qfl[ks][1] = *(const uint32_t*)(qgl + (r0 + 8) * 64 + kk);
            qfl[ks][2] = *(const uint32_t*)(qgl + r0 * 64 + kk + 8);
            qfl[ks][3] = *(const uint32_t*)(qgl + (r0 + 8) * 64 + kk + 8);
        }
    }

    float acc[8][4];
#pragma unroll
    for (int i = 0; i < 8; i++)
#pragma unroll
        for (int j = 0; j < 4; j++) acc[i][j] = 0.0f;
    float m0 = -1e30f, m1 = -1e30f, lsum0 = 0.0f, lsum1 = 0.0f;

    auto issue = [&](int kt) {
        const uint32_t st = sb + (kt & 1) * A_STAGE;
        const __nv_bfloat16* arrs[4] = {Kh, Kl, Vh, Vl};
        // 4 arrays x 64 rows x 8 cols of 16B = 2048 chunks; 8 per thread
#pragma unroll
        for (int i = 0; i < 8; i++) {
            const int c = tid + i * 256;
            const int arr = c >> 9;
            const int cc = c & 511;
            const int row = cc >> 3, col = cc & 7;
            cp_async16(st + arr * A_ARR + row * 144 + col * 16,
                       arrs[arr] + ((size_t)bh * S_LEN + kt * 64 + row) * 64 + col * 8);
        }
        // mask: 128 rows x 64 bytes = 512 chunks of 16B; 2 per thread
#pragma unroll
        for (int i = 0; i < 2; i++) {
            const int c = tid + i * 256;
            const int row = c >> 2, col = (c & 3) * 16;
            cp_async16(st + A_MASK_OFF + row * 64 + col,
                       maskb + ((size_t)b * S_LEN + q0 + row) * S_LEN + kt * 64 + col);
        }
        CP_COMMIT();
    };

    issue(0);

    const uint32_t klane = (uint32_t)((l & 7) + ((l >> 4) & 1) * 8) * 144 + ((l >> 3) & 1) * 16;
    const uint32_t vlane = (uint32_t)((l & 7) + ((l >> 3) & 1) * 8) * 144 + ((l >> 4) & 1) * 16;
    const int mrow = w * 16 + (l >> 2);
    const int mcol = 2 * (l & 3);

    for (int kt = 0; kt < 32; kt++) {
        if (kt + 1 < 32) { issue(kt + 1); CP_WAIT1(); } else { CP_WAIT0(); }
        __syncthreads();
        const uint32_t st = sb + (kt & 1) * A_STAGE;

        // ---- scores = Q K^T (hi/lo, 3 terms); N = 64 cols ----
        float sc[8][4];
#pragma unroll
        for (int i = 0; i < 8; i++) { sc[i][0] = sc[i][1] = sc[i][2] = sc[i][3] = 0.0f; }
#pragma unroll
        for (int ks = 0; ks < 4; ks++) {
#pragma unroll
            for (int nt2 = 0; nt2 < 4; nt2++) {
                uint32_t kh4[4], kl4[4];
                const uint32_t ao = st + (uint32_t)(nt2 * 16) * 144 + ks * 32 + klane;
                ldmx4(kh4, ao);
                ldmx4(kl4, ao + A_ARR);
                mma16816(sc[2 * nt2],     qfh[ks], kh4[0], kh4[1]);
                mma16816(sc[2 * nt2],     qfl[ks], kh4[0], kh4[1]);
                mma16816(sc[2 * nt2],     qfh[ks], kl4[0], kl4[1]);
                mma16816(sc[2 * nt2 + 1], qfh[ks], kh4[2], kh4[3]);
                mma16816(sc[2 * nt2 + 1], qfl[ks], kh4[2], kh4[3]);
                mma16816(sc[2 * nt2 + 1], qfh[ks], kl4[2], kl4[3]);
            }
        }

        // ---- scale + mask (byte tile, pitch 64) ----
#pragma unroll
        for (int nt = 0; nt < 8; nt++) {
            const uint32_t a0 = st + A_MASK_OFF + mrow * 64 + nt * 8 + mcol;
            unsigned short mm0, mm1;
            asm volatile("ld.shared.u16 %0, [%1];" : "=h"(mm0) : "r"(a0));
            asm volatile("ld.shared.u16 %0, [%1];" : "=h"(mm1) : "r"(a0 + 8 * 64));
            sc[nt][0] = (mm0 & 0xFF) ? MASK_VAL : sc[nt][0] * 0.125f;
            sc[nt][1] = (mm0 >> 8)   ? MASK_VAL : sc[nt][1] * 0.125f;
            sc[nt][2] = (mm1 & 0xFF) ? MASK_VAL : sc[nt][2] * 0.125f;
            sc[nt][3] = (mm1 >> 8)   ? MASK_VAL : sc[nt][3] * 0.125f;
        }

        // ---- online softmax ----
        float mx0 = sc[0][0], mx1 = sc[0][2];
#pragma unroll
        for (int nt = 0; nt < 8; nt++) {
            mx0 = fmaxf(mx0, fmaxf(sc[nt][0], sc[nt][1]));
            mx1 = fmaxf(mx1, fmaxf(sc[nt][2], sc[nt][3]));
        }
        mx0 = fmaxf(mx0, __shfl_xor_sync(0xFFFFFFFFu, mx0, 1));
        mx0 = fmaxf(mx0, __shfl_xor_sync(0xFFFFFFFFu, mx0, 2));
        mx1 = fmaxf(mx1, __shfl_xor_sync(0xFFFFFFFFu, mx1, 1));
        mx1 = fmaxf(mx1, __shfl_xor_sync(0xFFFFFFFFu, mx1, 2));

        const float nm0 = fmaxf(m0, mx0), nm1 = fmaxf(m1, mx1);
        const float cr0 = fexp(m0 - nm0), cr1 = fexp(m1 - nm1);
        m0 = nm0; m1 = nm1;

        float s0 = 0.0f, s1 = 0.0f;
#pragma unroll
        for (int nt = 0; nt < 8; nt++) {
            sc[nt][0] = fexp(sc[nt][0] - nm0); s0 += sc[nt][0];
            sc[nt][1] = fexp(sc[nt][1] - nm0); s0 += sc[nt][1];
            sc[nt][2] = fexp(sc[nt][2] - nm1); s1 += sc[nt][2];
            sc[nt][3] = fexp(sc[nt][3] - nm1); s1 += sc[nt][3];
        }
        s0 += __shfl_xor_sync(0xFFFFFFFFu, s0, 1);
        s0 += __shfl_xor_sync(0xFFFFFFFFu, s0, 2);
        s1 += __shfl_xor_sync(0xFFFFFFFFu, s1, 1);
        s1 += __shfl_xor_sync(0xFFFFFFFFu, s1, 2);
        lsum0 = lsum0 * cr0 + s0;
        lsum1 = lsum1 * cr1 + s1;
#pragma unroll
        for (int nt = 0; nt < 8; nt++) {
            acc[nt][0] *= cr0; acc[nt][1] *= cr0;
            acc[nt][2] *= cr1; acc[nt][3] *= cr1;
        }

        // ---- ctx += P V (64 tokens) ----
#pragma unroll
        for (int kt16 = 0; kt16 < 4; kt16++) {
            uint32_t ph[4], pl[4];
            split_hilo(sc[2 * kt16][0],     sc[2 * kt16][1],     ph[0], pl[0]);
            split_hilo(sc[2 * kt16][2],     sc[2 * kt16][3],     ph[1], pl[1]);
            split_hilo(sc[2 * kt16 + 1][0], sc[2 * kt16 + 1][1], ph[2], pl[2]);
            split_hilo(sc[2 * kt16 + 1][2], sc[2 * kt16 + 1][3], ph[3], pl[3]);
#pragma unroll
            for (int db = 0; db < 4; db++) {
                uint32_t vh4[4], vl4[4];
                const uint32_t ao = st + 2 * A_ARR + (uint32_t)(kt16 * 16) * 144 + db * 32 + vlane;
                ldmx4t(vh4, ao);
                ldmx4t(vl4, ao + A_ARR);
                mma16816(acc[2 * db],     ph, vh4[0], vh4[1]);
                mma16816(acc[2 * db],     pl, vh4[0], vh4[1]);
                mma16816(acc[2 * db],     ph, vl4[0], vl4[1]);
                mma16816(acc[2 * db + 1], ph, vh4[2], vh4[3]);
                mma16816(acc[2 * db + 1], pl, vh4[2], vh4[3]);
                mma16816(acc[2 * db + 1], ph, vl4[2], vl4[3]);
            }
        }
        __syncthreads();
    }

    // ---- normalize + write ctx as bf16 hi/lo ----
    const float i0 = 1.0f / lsum0, i1 = 1.0f / lsum1;
    const int srow = q0 + w * 16 + (l >> 2);
    const int colb = h * 64 + 2 * (l & 3);
#pragma unroll
    for (int nt = 0; nt < 8; nt++) {
        const int col = colb + nt * 8;
        uint32_t hiw, low;
        split_hilo(acc[nt][0] * i0, acc[nt][1] * i0, hiw, low);
        const size_t off0 = ((size_t)srow * 4 + b) * HID + col;
        *(uint32_t*)(ctxh + off0) = hiw;
        *(uint32_t*)(ctxl + off0) = low;
        split_hilo(acc[nt][2] * i1, acc[nt][3] * i1, hiw, low);
        const size_t off1 = ((size_t)(srow + 8) * 4 + b) * HID + col;
        *(uint32_t*)(ctxh + off1) = hiw;
        *(uint32_t*)(ctxl + off1) = low;
    }
}

// ---------------------------------------------------------------------------
// Launch
// ---------------------------------------------------------------------------
extern "C" void kernel_launch(void* const* d_in, const int* in_sizes, int n_in,
                              void* d_out, int out_size) {
    const float* hs      = (const float*)d_in[0];
    const void*  mask    = d_in[1];
    const float* W_qkv   = (const float*)d_in[2];
    const float* b_qkv   = (const float*)d_in[3];
    const float* W_dense = (const float*)d_in[4];
    const float* b_dense = (const float*)d_in[5];
    float* out = (float*)d_out;

    __nv_bfloat16 *pAh, *pAl, *pWqh, *pWql, *pWdh, *pWdl;
    __nv_bfloat16 *Qh, *Ql, *Kh, *Kl, *Vh, *Vl;
    unsigned char* masku8;
    cudaGetSymbolAddress((void**)&pAh, g_pA_hi);
    cudaGetSymbolAddress((void**)&pAl, g_pA_lo);
    cudaGetSymbolAddress((void**)&pWqh, g_pWq_hi);
    cudaGetSymbolAddress((void**)&pWql, g_pWq_lo);
    cudaGetSymbolAddress((void**)&pWdh, g_pWd_hi);
    cudaGetSymbolAddress((void**)&pWdl, g_pWd_lo);
    cudaGetSymbolAddress((void**)&Qh, g_Qh);
    cudaGetSymbolAddress((void**)&Ql, g_Ql);
    cudaGetSymbolAddress((void**)&Kh, g_Kh);
    cudaGetSymbolAddress((void**)&Kl, g_Kl);
    cudaGetSymbolAddress((void**)&Vh, g_Vh);
    cudaGetSymbolAddress((void**)&Vl, g_Vl);
    cudaGetSymbolAddress((void**)&masku8, g_mask_u8);

    cudaFuncSetAttribute(gemm_mma, cudaFuncAttributeMaxDynamicSharedMemorySize, GT_SMEM);
    cudaFuncSetAttribute(attention_mma, cudaFuncAttributeMaxDynamicSharedMemorySize, A_SMEM);

    // 0) mask dtype + byte conversion
    detect_mask_dtype<<<1, 32>>>((const int*)mask);
    convert_mask<<<(BATCH * S_LEN * S_LEN / 4) / 256, 256>>>(mask, masku8);

    // 1) pack hs + W_qkv
    pack_hilo<<<(M_ROWS * HID / 4) / 256, 256>>>(hs, pAh, pAl);
    pack_hilo<<<(QKV_N * HID / 4) / 256, 256>>>(W_qkv, pWqh, pWql);

    // 2) QKV GEMM -> split bf16 hi/lo Q/K/V
    gemm_mma<<<dim3(QKV_N / 128, M_ROWS / 128), 256, GT_SMEM>>>(
        pAh, pAl, pWqh, pWql, b_qkv, nullptr, QKV_N, 1, Qh, Ql, Kh, Kl, Vh, Vl);

    // 3) tensor-core flash attention -> ctx hi/lo (into pA buffers)
    attention_mma<<<dim3(S_LEN / 128, BATCH * NHEADS), 256, A_SMEM>>>(
        masku8, Qh, Ql, Kh, Kl, Vh, Vl, pAh, pAl);

    // 4) pack W_dense + dense GEMM -> out
    pack_hilo<<<(HID * HID / 4) / 256, 256>>>(W_dense, pWdh, pWdl);
    gemm_mma<<<dim3(HID / 128, M_ROWS / 128), 256, GT_SMEM>>>(
        pAh, pAl, pWdh, pWdl, b_dense, out, HID, 0,
        nullptr, nullptr, nullptr, nullptr, nullptr, nullptr);
}

// round 10
// speedup vs baseline: 8.1817x; 1.0601x over previous
#include <cuda_runtime.h>
#include <cuda_bf16.h>
#include <math.h>
#include <stdint.h>

#define S_LEN 2048
#define BATCH 4
#define HID 1024
#define NHEADS 16
#define HDIM 64
#define M_ROWS (S_LEN * BATCH)   // 8192
#define QKV_N (3 * HID)          // 3072
#define GK HID                   // K dim of both GEMMs = 1024
#define SCALE_L2E 0.18033688011112043f   // 0.125 * log2(e)
#define MASK_L2  (-14426.950408889634f)  // -10000 * log2(e)

// ---------------- scratch (allocation-free: device globals) ----------------
__device__ int g_mask_is_i32;
__device__ unsigned char g_mask_u8[(size_t)BATCH * S_LEN * S_LEN];   // 16.7 MB

// Q/K/V bf16 hi/lo, layout [bh=b*16+h][token][64]
#define QKV_ELEMS ((size_t)64 * S_LEN * HDIM)
__device__ __align__(16) __nv_bfloat16 g_Qh[QKV_ELEMS], g_Ql[QKV_ELEMS];
__device__ __align__(16) __nv_bfloat16 g_Kh[QKV_ELEMS], g_Kl[QKV_ELEMS];
__device__ __align__(16) __nv_bfloat16 g_Vh[QKV_ELEMS], g_Vl[QKV_ELEMS];

// A-operand packs (hs for QKV GEMM; later overwritten with ctx for dense GEMM)
__device__ __align__(16) __nv_bfloat16 g_pA_hi[(size_t)M_ROWS * HID];
__device__ __align__(16) __nv_bfloat16 g_pA_lo[(size_t)M_ROWS * HID];
__device__ __align__(16) __nv_bfloat16 g_pWq_hi[(size_t)QKV_N * HID];
__device__ __align__(16) __nv_bfloat16 g_pWq_lo[(size_t)QKV_N * HID];
__device__ __align__(16) __nv_bfloat16 g_pWd_hi[(size_t)HID * HID];
__device__ __align__(16) __nv_bfloat16 g_pWd_lo[(size_t)HID * HID];

// ---------------- helpers ----------------
__device__ __forceinline__ uint32_t smem_to_u32(const void* p) {
    uint32_t a;
    asm("{ .reg .u64 t; cvta.to.shared.u64 t, %1; cvt.u32.u64 %0, t; }" : "=r"(a) : "l"(p));
    return a;
}
__device__ __forceinline__ void cp_async16(uint32_t dst, const void* src) {
    asm volatile("cp.async.cg.shared.global [%0], [%1], 16;" :: "r"(dst), "l"(src));
}
#define CP_COMMIT() asm volatile("cp.async.commit_group;" ::: "memory")
#define CP_WAIT0()  asm volatile("cp.async.wait_group 0;" ::: "memory")
#define CP_WAIT1()  asm volatile("cp.async.wait_group 1;" ::: "memory")

__device__ __forceinline__ void ldmx4(uint32_t* r, uint32_t addr) {
    asm volatile("ldmatrix.sync.aligned.m8n8.x4.shared.b16 {%0,%1,%2,%3}, [%4];"
                 : "=r"(r[0]), "=r"(r[1]), "=r"(r[2]), "=r"(r[3]) : "r"(addr));
}
__device__ __forceinline__ void ldmx4t(uint32_t* r, uint32_t addr) {
    asm volatile("ldmatrix.sync.aligned.m8n8.x4.trans.shared.b16 {%0,%1,%2,%3}, [%4];"
                 : "=r"(r[0]), "=r"(r[1]), "=r"(r[2]), "=r"(r[3]) : "r"(addr));
}
__device__ __forceinline__ void mma16816(float* c, const uint32_t* a, uint32_t b0, uint32_t b1) {
    asm volatile(
        "mma.sync.aligned.m16n8k16.row.col.f32.bf16.bf16.f32 "
        "{%0,%1,%2,%3}, {%4,%5,%6,%7}, {%8,%9}, {%0,%1,%2,%3};"
        : "+f"(c[0]), "+f"(c[1]), "+f"(c[2]), "+f"(c[3])
        : "r"(a[0]), "r"(a[1]), "r"(a[2]), "r"(a[3]), "r"(b0), "r"(b1));
}
__device__ __forceinline__ uint32_t packbf2(float vhigh, float vlow) {
    uint32_t r;
    asm("cvt.rn.bf16x2.f32 %0, %1, %2;" : "=r"(r) : "f"(vhigh), "f"(vlow));
    return r;
}
__device__ __forceinline__ void split_hilo(float v0, float v1, uint32_t& hi, uint32_t& lo) {
    hi = packbf2(v1, v0);
    const float h0 = __int_as_float(hi << 16);
    const float h1 = __int_as_float(hi & 0xFFFF0000u);
    lo = packbf2(v1 - h1, v0 - h0);
}
// single-instruction exp2 on the MUFU pipe
__device__ __forceinline__ float ex2(float x) {
    float y;
    asm("ex2.approx.f32 %0, %1;" : "=f"(y) : "f"(x));
    return y;
}

// ---------------------------------------------------------------------------
// Mask dtype detect + byte conversion
// ---------------------------------------------------------------------------
__global__ void detect_mask_dtype(const int* __restrict__ m) {
    int bad = 0;
#pragma unroll
    for (int i = 0; i < 32; i++) {
        unsigned v = (unsigned)m[threadIdx.x * 32 + i];
        bad |= (v > 1u);
    }
    unsigned any = __ballot_sync(0xFFFFFFFFu, bad);
    if (threadIdx.x == 0) g_mask_is_i32 = (any == 0) ? 1 : 0;
}

__global__ void __launch_bounds__(256)
convert_mask(const void* __restrict__ raw, unsigned char* __restrict__ out) {
    const size_t i = (size_t)blockIdx.x * 256 + threadIdx.x;
    uchar4 o;
    if (g_mask_is_i32) {
        const int4 v = ((const int4*)raw)[i];
        o = make_uchar4((unsigned char)v.x, (unsigned char)v.y,
                        (unsigned char)v.z, (unsigned char)v.w);
    } else {
        o = ((const uchar4*)raw)[i];
    }
    ((uchar4*)out)[i] = o;
}

// ---------------------------------------------------------------------------
// Pack fp32 -> hi/lo bf16 (row-major flat)
// ---------------------------------------------------------------------------
__global__ void __launch_bounds__(256)
pack_hilo(const float* __restrict__ src, __nv_bfloat16* __restrict__ hi,
          __nv_bfloat16* __restrict__ lo) {
    const size_t idx = (size_t)blockIdx.x * 256 + threadIdx.x;
    const float4 v = *(const float4*)(src + idx * 4);
    uint32_t h0, l0, h1, l1;
    split_hilo(v.x, v.y, h0, l0);
    split_hilo(v.z, v.w, h1, l1);
    *(uint2*)(hi + idx * 4) = make_uint2(h0, h1);
    *(uint2*)(lo + idx * 4) = make_uint2(l0, l1);
}

// ---------------------------------------------------------------------------
// bf16 hi/lo GEMM via mma.sync (unchanged — 57.5% tensor)
// ---------------------------------------------------------------------------
#define GP 80
#define GT_TILE (128 * GP)
#define GT_STAGE (4 * GT_TILE)
#define GT_SMEM (2 * GT_STAGE)

__global__ void __launch_bounds__(256)
gemm_mma(const __nv_bfloat16* __restrict__ Ahi, const __nv_bfloat16* __restrict__ Alo,
         const __nv_bfloat16* __restrict__ Bhi, const __nv_bfloat16* __restrict__ Blo,
         const float* __restrict__ bias, float* __restrict__ C, int n_dim, int epi_mode,
         __nv_bfloat16* qh, __nv_bfloat16* ql, __nv_bfloat16* kh,
         __nv_bfloat16* kl, __nv_bfloat16* vh, __nv_bfloat16* vl) {
    extern __shared__ __align__(1024) char smem[];
    const uint32_t sb = smem_to_u32(smem);
    const int tid = threadIdx.x;
    const int bx = blockIdx.x, by = blockIdx.y;
    const int w = tid >> 5, l = tid & 31;
    const int wm = w >> 1, wn = w & 1;

    const int c0row = tid >> 2,        c0col = tid & 3;
    const int c1row = (tid + 256) >> 2, c1col = (tid + 256) & 3;

    const __nv_bfloat16* srcs[4] = {Ahi, Alo, Bhi, Blo};
    const size_t rowbase[4] = {(size_t)by * 128, (size_t)by * 128,
                               (size_t)bx * 128, (size_t)bx * 128};

    float acc[2][8][4];
#pragma unroll
    for (int i = 0; i < 2; i++)
#pragma unroll
        for (int j = 0; j < 8; j++)
#pragma unroll
            for (int q = 0; q < 4; q++) acc[i][j][q] = 0.0f;

    const uint32_t a_lane = (uint32_t)(l & 15) * GP + ((l >> 4) & 1) * 16;
    const uint32_t b_lane = (uint32_t)((l & 7) + ((l >> 4) & 1) * 8) * GP + ((l >> 3) & 1) * 16;

    auto issue = [&](int s, int k0) {
        const uint32_t st = sb + s * GT_STAGE;
#pragma unroll
        for (int t = 0; t < 4; t++) {
            const __nv_bfloat16* base = srcs[t] + (rowbase[t]) * GK + k0;
            cp_async16(st + t * GT_TILE + c0row * GP + c0col * 16,
                       base + (size_t)c0row * GK + c0col * 8);
            cp_async16(st + t * GT_TILE + c1row * GP + c1col * 16,
                       base + (size_t)c1row * GK + c1col * 8);
        }
        CP_COMMIT();
    };

    issue(0, 0);

    for (int kt = 0; kt < GK / 32; kt++) {
        const int s = kt & 1;
        CP_WAIT0();
        __syncthreads();
        if (kt + 1 < GK / 32) issue(s ^ 1, (kt + 1) * 32);

        const uint32_t st = sb + s * GT_STAGE;
#pragma unroll
        for (int ks = 0; ks < 2; ks++) {
            const uint32_t kb = ks * 32;
            uint32_t ah[2][4], al[2][4], bh2[4][4], bl2[4][4];
#pragma unroll
            for (int mi = 0; mi < 2; mi++) {
                const uint32_t ao = (uint32_t)(wm * 32 + mi * 16) * GP + kb + a_lane;
                ldmx4(ah[mi], st + ao);
                ldmx4(al[mi], st + GT_TILE + ao);
            }
#pragma unroll
            for (int bi = 0; bi < 4; bi++) {
                const uint32_t bo = (uint32_t)(wn * 64 + bi * 16) * GP + kb + b_lane;
                ldmx4(bh2[bi], st + 2 * GT_TILE + bo);
                ldmx4(bl2[bi], st + 3 * GT_TILE + bo);
            }
#pragma unroll
            for (int mi = 0; mi < 2; mi++)
#pragma unroll
                for (int bi = 0; bi < 4; bi++)
#pragma unroll
                    for (int t = 0; t < 2; t++) {
                        float* c = acc[mi][bi * 2 + t];
                        mma16816(c, ah[mi], bh2[bi][t * 2], bh2[bi][t * 2 + 1]);
                        mma16816(c, al[mi], bh2[bi][t * 2], bh2[bi][t * 2 + 1]);
                        mma16816(c, ah[mi], bl2[bi][t * 2], bl2[bi][t * 2 + 1]);
                    }
        }
        __syncthreads();
    }

    const int mg = by * 128 + wm * 32 + (l >> 2);
    const int ng0 = bx * 128 + wn * 64 + (l & 3) * 2;

    if (epi_mode == 0) {
#pragma unroll
        for (int mi = 0; mi < 2; mi++) {
#pragma unroll
            for (int ni = 0; ni < 8; ni++) {
                const int n = ng0 + ni * 8;
                const float2 bv = *(const float2*)(bias + n);
                const int m0 = mg + mi * 16;
                *(float2*)(C + (size_t)m0 * n_dim + n) =
                    make_float2(acc[mi][ni][0] + bv.x, acc[mi][ni][1] + bv.y);
                *(float2*)(C + (size_t)(m0 + 8) * n_dim + n) =
                    make_float2(acc[mi][ni][2] + bv.x, acc[mi][ni][3] + bv.y);
            }
        }
    } else {
#pragma unroll
        for (int mi = 0; mi < 2; mi++) {
#pragma unroll
            for (int ni = 0; ni < 8; ni++) {
                const int n = ng0 + ni * 8;
                const int hh = n / 192;
                const int r = n - hh * 192;
                const int kind = r >> 6;
                const int d = r & 63;
                const float b0 = bias[n], b1 = bias[n + 1];
                __nv_bfloat16* dsth = (kind == 0) ? qh : (kind == 1) ? kh : vh;
                __nv_bfloat16* dstl = (kind == 0) ? ql : (kind == 1) ? kl : vl;
#pragma unroll
                for (int hf = 0; hf < 2; hf++) {
                    const int m = mg + mi * 16 + hf * 8;
                    const int s = m >> 2, bb = m & 3;
                    const size_t off = ((size_t)(bb * NHEADS + hh) * S_LEN + s) * 64 + d;
                    uint32_t hiw, low;
                    split_hilo(acc[mi][ni][hf * 2 + 0] + b0,
                               acc[mi][ni][hf * 2 + 1] + b1, hiw, low);
                    *(uint32_t*)(dsth + off) = hiw;
                    *(uint32_t*)(dstl + off) = low;
                }
            }
        }
    }
}

// ---------------------------------------------------------------------------
// Tensor-core flash attention v3: log2-domain softmax on MUFU (ex2.approx).
// K-tile 64, 2 CTAs/SM. Grid (16 qtiles, 64 bh), 256 threads (8 warps).
// ---------------------------------------------------------------------------
#define A_ARR (64 * 144)                  // 9216 B per array
#define A_MASK_OFF (4 * A_ARR)            // 36864
#define A_STAGE (A_MASK_OFF + 128 * 64)   // 45056
#define A_SMEM (2 * A_STAGE)              // 90112 -> 2 CTAs/SM

__global__ void __launch_bounds__(256, 2)
attention_mma(const unsigned char* __restrict__ maskb,
              const __nv_bfloat16* __restrict__ Qh, const __nv_bfloat16* __restrict__ Ql,
              const __nv_bfloat16* __restrict__ Kh, const __nv_bfloat16* __restrict__ Kl,
              const __nv_bfloat16* __restrict__ Vh, const __nv_bfloat16* __restrict__ Vl,
              __nv_bfloat16* __restrict__ ctxh, __nv_bfloat16* __restrict__ ctxl) {
    extern __shared__ __align__(1024) char smem[];
    const uint32_t sb = smem_to_u32(smem);
    const int tid = threadIdx.x, w = tid >> 5, l = tid & 31;
    const int qt = blockIdx.x, bh = blockIdx.y;
    const int b = bh >> 4, h = bh & 15;
    const int q0 = qt * 128;

    // Q fragments straight from gmem
    uint32_t qfh[4][4], qfl[4][4];
    {
        const __nv_bfloat16* qgh = Qh + ((size_t)bh * S_LEN + q0 + w * 16) * 64;
        const __nv_bfloat16* qgl = Ql + ((size_t)bh * S_LEN + q0 + w * 16) * 64;
        const int r0 = l >> 2, k0 = 2 * (l & 3);
#pragma unroll
        for (int ks = 0; ks < 4; ks++) {
            const int kk = ks * 16 + k0;
            qfh[ks][0] = *(const uint32_t*)(qgh + r0 * 64 + kk);
            qfh[ks][1] = *(const uint32_t*)(qgh + (r0 + 8) * 64 + kk);
            qfh[ks][2] = *(const uint32_t*)(qgh + r0 * 64 + kk + 8);
            qfh[ks][3] = *(const uint32_t*)(qgh + (r0 + 8) * 64 + kk + 8);
            qfl[ks][0] = *(const uint32_t*)(qgl + r0 * 64 + kk);
            qfl[ks][1] = *(const uint32_t*)(qgl + (r0 + 8) * 64 + kk);
            qfl[ks][2] = *(const uint32_t*)(qgl + r0 * 64 + kk + 8);
            qfl[ks][3] = *(const uint32_t*)(qgl + (r0 + 8) * 64 + kk + 8);
        }
    }

    float acc[8][4];
#pragma unroll
    for (int i = 0; i < 8; i++)
#pragma unroll
        for (int j = 0; j < 4; j++) acc[i][j] = 0.0f;
    // running max in log2 domain
    float m0 = -1e30f, m1 = -1e30f, lsum0 = 0.0f, lsum1 = 0.0f;

    auto issue = [&](int kt) {
        const uint32_t st = sb + (kt & 1) * A_STAGE;
        const __nv_bfloat16* arrs[4] = {Kh, Kl, Vh, Vl};
#pragma unroll
        for (int i = 0; i < 8; i++) {
            const int c = tid + i * 256;
            const int arr = c >> 9;
            const int cc = c & 511;
            const int row = cc >> 3, col = cc & 7;
            cp_async16(st + arr * A_ARR + row * 144 + col * 16,
                       arrs[arr] + ((size_t)bh * S_LEN + kt * 64 + row) * 64 + col * 8);
        }
#pragma unroll
        for (int i = 0; i < 2; i++) {
            const int c = tid + i * 256;
            const int row = c >> 2, col = (c & 3) * 16;
            cp_async16(st + A_MASK_OFF + row * 64 + col,
                       maskb + ((size_t)b * S_LEN + q0 + row) * S_LEN + kt * 64 + col);
        }
        CP_COMMIT();
    };

    issue(0);

    const uint32_t klane = (uint32_t)((l & 7) + ((l >> 4) & 1) * 8) * 144 + ((l >> 3) & 1) * 16;
    const uint32_t vlane = (uint32_t)((l & 7) + ((l >> 3) & 1) * 8) * 144 + ((l >> 4) & 1) * 16;
    const int mrow = w * 16 + (l >> 2);
    const int mcol = 2 * (l & 3);

    for (int kt = 0; kt < 32; kt++) {
        if (kt + 1 < 32) { issue(kt + 1); CP_WAIT1(); } else { CP_WAIT0(); }
        __syncthreads();
        const uint32_t st = sb + (kt & 1) * A_STAGE;

        // ---- scores = Q K^T (hi/lo, 3 terms) ----
        float sc[8][4];
#pragma unroll
        for (int i = 0; i < 8; i++) { sc[i][0] = sc[i][1] = sc[i][2] = sc[i][3] = 0.0f; }
#pragma unroll
        for (int ks = 0; ks < 4; ks++) {
#pragma unroll
            for (int nt2 = 0; nt2 < 4; nt2++) {
                uint32_t kh4[4], kl4[4];
                const uint32_t ao = st + (uint32_t)(nt2 * 16) * 144 + ks * 32 + klane;
                ldmx4(kh4, ao);
                ldmx4(kl4, ao + A_ARR);
                mma16816(sc[2 * nt2],     qfh[ks], kh4[0], kh4[1]);
                mma16816(sc[2 * nt2],     qfl[ks], kh4[0], kh4[1]);
                mma16816(sc[2 * nt2],     qfh[ks], kl4[0], kl4[1]);
                mma16816(sc[2 * nt2 + 1], qfh[ks], kh4[2], kh4[3]);
                mma16816(sc[2 * nt2 + 1], qfl[ks], kh4[2], kh4[3]);
                mma16816(sc[2 * nt2 + 1], qfh[ks], kl4[2], kl4[3]);
            }
        }

        // ---- scale+mask into log2 domain ----
#pragma unroll
        for (int nt = 0; nt < 8; nt++) {
            const uint32_t a0 = st + A_MASK_OFF + mrow * 64 + nt * 8 + mcol;
            unsigned short mm0, mm1;
            asm volatile("ld.shared.u16 %0, [%1];" : "=h"(mm0) : "r"(a0));
            asm volatile("ld.shared.u16 %0, [%1];" : "=h"(mm1) : "r"(a0 + 8 * 64));
            sc[nt][0] = (mm0 & 0xFF) ? MASK_L2 : sc[nt][0] * SCALE_L2E;
            sc[nt][1] = (mm0 >> 8)   ? MASK_L2 : sc[nt][1] * SCALE_L2E;
            sc[nt][2] = (mm1 & 0xFF) ? MASK_L2 : sc[nt][2] * SCALE_L2E;
            sc[nt][3] = (mm1 >> 8)   ? MASK_L2 : sc[nt][3] * SCALE_L2E;
        }

        // ---- online softmax (log2 domain, ex2 on MUFU) ----
        float mx0 = sc[0][0], mx1 = sc[0][2];
#pragma unroll
        for (int nt = 0; nt < 8; nt++) {
            mx0 = fmaxf(mx0, fmaxf(sc[nt][0], sc[nt][1]));
            mx1 = fmaxf(mx1, fmaxf(sc[nt][2], sc[nt][3]));
        }
        mx0 = fmaxf(mx0, __shfl_xor_sync(0xFFFFFFFFu, mx0, 1));
        mx0 = fmaxf(mx0, __shfl_xor_sync(0xFFFFFFFFu, mx0, 2));
        mx1 = fmaxf(mx1, __shfl_xor_sync(0xFFFFFFFFu, mx1, 1));
        mx1 = fmaxf(mx1, __shfl_xor_sync(0xFFFFFFFFu, mx1, 2));

        const float nm0 = fmaxf(m0, mx0), nm1 = fmaxf(m1, mx1);
        const float cr0 = ex2(m0 - nm0), cr1 = ex2(m1 - nm1);
        m0 = nm0; m1 = nm1;

        float s0 = 0.0f, s1 = 0.0f;
#pragma unroll
        for (int nt = 0; nt < 8; nt++) {
            sc[nt][0] = ex2(sc[nt][0] - nm0); s0 += sc[nt][0];
            sc[nt][1] = ex2(sc[nt][1] - nm0); s0 += sc[nt][1];
            sc[nt][2] = ex2(sc[nt][2] - nm1); s1 += sc[nt][2];
            sc[nt][3] = ex2(sc[nt][3] - nm1); s1 += sc[nt][3];
        }
        s0 += __shfl_xor_sync(0xFFFFFFFFu, s0, 1);
        s0 += __shfl_xor_sync(0xFFFFFFFFu, s0, 2);
        s1 += __shfl_xor_sync(0xFFFFFFFFu, s1, 1);
        s1 += __shfl_xor_sync(0xFFFFFFFFu, s1, 2);
        lsum0 = lsum0 * cr0 + s0;
        lsum1 = lsum1 * cr1 + s1;
#pragma unroll
        for (int nt = 0; nt < 8; nt++) {
            acc[nt][0] *= cr0; acc[nt][1] *= cr0;
            acc[nt][2] *= cr1; acc[nt][3] *= cr1;
        }

        // ---- ctx += P V (hi/lo, 3 terms) ----
#pragma unroll
        for (int kt16 = 0; kt16 < 4; kt16++) {
            uint32_t ph[4], pl[4];
            split_hilo(sc[2 * kt16][0],     sc[2 * kt16][1],     ph[0], pl[0]);
            split_hilo(sc[2 * kt16][2],     sc[2 * kt16][3],     ph[1], pl[1]);
            split_hilo(sc[2 * kt16 + 1][0], sc[2 * kt16 + 1][1], ph[2], pl[2]);
            split_hilo(sc[2 * kt16 + 1][2], sc[2 * kt16 + 1][3], ph[3], pl[3]);
#pragma unroll
            for (int db = 0; db < 4; db++) {
                uint32_t vh4[4], vl4[4];
                const uint32_t ao = st + 2 * A_ARR + (uint32_t)(kt16 * 16) * 144 + db * 32 + vlane;
                ldmx4t(vh4, ao);
                ldmx4t(vl4, ao + A_ARR);
                mma16816(acc[2 * db],     ph, vh4[0], vh4[1]);
                mma16816(acc[2 * db],     pl, vh4[0], vh4[1]);
                mma16816(acc[2 * db],     ph, vl4[0], vl4[1]);
                mma16816(acc[2 * db + 1], ph, vh4[2], vh4[3]);
                mma16816(acc[2 * db + 1], pl, vh4[2], vh4[3]);
                mma16816(acc[2 * db + 1], ph, vl4[2], vl4[3]);
            }
        }
        __syncthreads();
    }

    // ---- normalize + write ctx as bf16 hi/lo ----
    const float i0 = 1.0f / lsum0, i1 = 1.0f / lsum1;
    const int srow = q0 + w * 16 + (l >> 2);
    const int colb = h * 64 + 2 * (l & 3);
#pragma unroll
    for (int nt = 0; nt < 8; nt++) {
        const int col = colb + nt * 8;
        uint32_t hiw, low;
        split_hilo(acc[nt][0] * i0, acc[nt][1] * i0, hiw, low);
        const size_t off0 = ((size_t)srow * 4 + b) * HID + col;
        *(uint32_t*)(ctxh + off0) = hiw;
        *(uint32_t*)(ctxl + off0) = low;
        split_hilo(acc[nt][2] * i1, acc[nt][3] * i1, hiw, low);
        const size_t off1 = ((size_t)(srow + 8) * 4 + b) * HID + col;
        *(uint32_t*)(ctxh + off1) = hiw;
        *(uint32_t*)(ctxl + off1) = low;
    }
}

// ---------------------------------------------------------------------------
// Launch
// ---------------------------------------------------------------------------
extern "C" void kernel_launch(void* const* d_in, const int* in_sizes, int n_in,
                              void* d_out, int out_size) {
    const float* hs      = (const float*)d_in[0];
    const void*  mask    = d_in[1];
    const float* W_qkv   = (const float*)d_in[2];
    const float* b_qkv   = (const float*)d_in[3];
    const float* W_dense = (const float*)d_in[4];
    const float* b_dense = (const float*)d_in[5];
    float* out = (float*)d_out;

    __nv_bfloat16 *pAh, *pAl, *pWqh, *pWql, *pWdh, *pWdl;
    __nv_bfloat16 *Qh, *Ql, *Kh, *Kl, *Vh, *Vl;
    unsigned char* masku8;
    cudaGetSymbolAddress((void**)&pAh, g_pA_hi);
    cudaGetSymbolAddress((void**)&pAl, g_pA_lo);
    cudaGetSymbolAddress((void**)&pWqh, g_pWq_hi);
    cudaGetSymbolAddress((void**)&pWql, g_pWq_lo);
    cudaGetSymbolAddress((void**)&pWdh, g_pWd_hi);
    cudaGetSymbolAddress((void**)&pWdl, g_pWd_lo);
    cudaGetSymbolAddress((void**)&Qh, g_Qh);
    cudaGetSymbolAddress((void**)&Ql, g_Ql);
    cudaGetSymbolAddress((void**)&Kh, g_Kh);
    cudaGetSymbolAddress((void**)&Kl, g_Kl);
    cudaGetSymbolAddress((void**)&Vh, g_Vh);
    cudaGetSymbolAddress((void**)&Vl, g_Vl);
    cudaGetSymbolAddress((void**)&masku8, g_mask_u8);

    cudaFuncSetAttribute(gemm_mma, cudaFuncAttributeMaxDynamicSharedMemorySize, GT_SMEM);
    cudaFuncSetAttribute(attention_mma, cudaFuncAttributeMaxDynamicSharedMemorySize, A_SMEM);

    // 0) mask dtype + byte conversion
    detect_mask_dtype<<<1, 32>>>((const int*)mask);
    convert_mask<<<(BATCH * S_LEN * S_LEN / 4) / 256, 256>>>(mask, masku8);

    // 1) pack hs + W_qkv
    pack_hilo<<<(M_ROWS * HID / 4) / 256, 256>>>(hs, pAh, pAl);
    pack_hilo<<<(QKV_N * HID / 4) / 256, 256>>>(W_qkv, pWqh, pWql);

    // 2) QKV GEMM -> split bf16 hi/lo Q/K/V
    gemm_mma<<<dim3(QKV_N / 128, M_ROWS / 128), 256, GT_SMEM>>>(
        pAh, pAl, pWqh, pWql, b_qkv, nullptr, QKV_N, 1, Qh, Ql, Kh, Kl, Vh, Vl);

    // 3) tensor-core flash attention -> ctx hi/lo (into pA buffers)
    attention_mma<<<dim3(S_LEN / 128, BATCH * NHEADS), 256, A_SMEM>>>(
        masku8, Qh, Ql, Kh, Kl, Vh, Vl, pAh, pAl);

    // 4) pack W_dense + dense GEMM -> out
    pack_hilo<<<(HID * HID / 4) / 256, 256>>>(W_dense, pWdh, pWdl);
    gemm_mma<<<dim3(HID / 128, M_ROWS / 128), 256, GT_SMEM>>>(
        pAh, pAl, pWdh, pWdl, b_dense, out, HID, 0,
        nullptr, nullptr, nullptr, nullptr, nullptr, nullptr);
}

// round 11
// speedup vs baseline: 9.2367x; 1.1289x over previous
#include <cuda_runtime.h>
#include <cuda_bf16.h>
#include <math.h>
#include <stdint.h>

#define S_LEN 2048
#define BATCH 4
#define HID 1024
#define NHEADS 16
#define HDIM 64
#define M_ROWS (S_LEN * BATCH)   // 8192
#define QKV_N (3 * HID)          // 3072
#define GK HID                   // K dim of both GEMMs = 1024
#define SCALE_L2E 0.18033688011112043f   // 0.125 * log2(e)
#define MASK_L2  (-14426.950408889634f)  // -10000 * log2(e)

// ---------------- scratch (allocation-free: device globals) ----------------
__device__ int g_mask_is_i32;
// fragment-layout mask bits: word (b,qt,kt,tid) = the 32 bools that thread
// tid of CTA (qt,bh with batch b) needs in iteration kt. 2 MB.
__device__ uint32_t g_mask_bits[(size_t)BATCH * 16 * 32 * 256];

// Q/K/V bf16 hi/lo, layout [bh=b*16+h][token][64]
#define QKV_ELEMS ((size_t)64 * S_LEN * HDIM)
__device__ __align__(16) __nv_bfloat16 g_Qh[QKV_ELEMS], g_Ql[QKV_ELEMS];
__device__ __align__(16) __nv_bfloat16 g_Kh[QKV_ELEMS], g_Kl[QKV_ELEMS];
__device__ __align__(16) __nv_bfloat16 g_Vh[QKV_ELEMS], g_Vl[QKV_ELEMS];

// A-operand packs (hs for QKV GEMM; later overwritten with ctx for dense GEMM)
__device__ __align__(16) __nv_bfloat16 g_pA_hi[(size_t)M_ROWS * HID];
__device__ __align__(16) __nv_bfloat16 g_pA_lo[(size_t)M_ROWS * HID];
__device__ __align__(16) __nv_bfloat16 g_pWq_hi[(size_t)QKV_N * HID];
__device__ __align__(16) __nv_bfloat16 g_pWq_lo[(size_t)QKV_N * HID];
__device__ __align__(16) __nv_bfloat16 g_pWd_hi[(size_t)HID * HID];
__device__ __align__(16) __nv_bfloat16 g_pWd_lo[(size_t)HID * HID];

// ---------------- helpers ----------------
__device__ __forceinline__ uint32_t smem_to_u32(const void* p) {
    uint32_t a;
    asm("{ .reg .u64 t; cvta.to.shared.u64 t, %1; cvt.u32.u64 %0, t; }" : "=r"(a) : "l"(p));
    return a;
}
__device__ __forceinline__ void cp_async16(uint32_t dst, const void* src) {
    asm volatile("cp.async.cg.shared.global [%0], [%1], 16;" :: "r"(dst), "l"(src));
}
#define CP_COMMIT() asm volatile("cp.async.commit_group;" ::: "memory")
#define CP_WAIT0()  asm volatile("cp.async.wait_group 0;" ::: "memory")
#define CP_WAIT1()  asm volatile("cp.async.wait_group 1;" ::: "memory")

__device__ __forceinline__ void ldmx4(uint32_t* r, uint32_t addr) {
    asm volatile("ldmatrix.sync.aligned.m8n8.x4.shared.b16 {%0,%1,%2,%3}, [%4];"
                 : "=r"(r[0]), "=r"(r[1]), "=r"(r[2]), "=r"(r[3]) : "r"(addr));
}
__device__ __forceinline__ void ldmx4t(uint32_t* r, uint32_t addr) {
    asm volatile("ldmatrix.sync.aligned.m8n8.x4.trans.shared.b16 {%0,%1,%2,%3}, [%4];"
                 : "=r"(r[0]), "=r"(r[1]), "=r"(r[2]), "=r"(r[3]) : "r"(addr));
}
__device__ __forceinline__ void mma16816(float* c, const uint32_t* a, uint32_t b0, uint32_t b1) {
    asm volatile(
        "mma.sync.aligned.m16n8k16.row.col.f32.bf16.bf16.f32 "
        "{%0,%1,%2,%3}, {%4,%5,%6,%7}, {%8,%9}, {%0,%1,%2,%3};"
        : "+f"(c[0]), "+f"(c[1]), "+f"(c[2]), "+f"(c[3])
        : "r"(a[0]), "r"(a[1]), "r"(a[2]), "r"(a[3]), "r"(b0), "r"(b1));
}
__device__ __forceinline__ uint32_t packbf2(float vhigh, float vlow) {
    uint32_t r;
    asm("cvt.rn.bf16x2.f32 %0, %1, %2;" : "=r"(r) : "f"(vhigh), "f"(vlow));
    return r;
}
__device__ __forceinline__ void split_hilo(float v0, float v1, uint32_t& hi, uint32_t& lo) {
    hi = packbf2(v1, v0);
    const float h0 = __int_as_float(hi << 16);
    const float h1 = __int_as_float(hi & 0xFFFF0000u);
    lo = packbf2(v1 - h1, v0 - h0);
}
__device__ __forceinline__ float ex2(float x) {
    float y;
    asm("ex2.approx.f32 %0, %1;" : "=f"(y) : "f"(x));
    return y;
}

// ---------------------------------------------------------------------------
// Mask dtype detect
// ---------------------------------------------------------------------------
__global__ void detect_mask_dtype(const int* __restrict__ m) {
    int bad = 0;
#pragma unroll
    for (int i = 0; i < 32; i++) {
        unsigned v = (unsigned)m[threadIdx.x * 32 + i];
        bad |= (v > 1u);
    }
    unsigned any = __ballot_sync(0xFFFFFFFFu, bad);
    if (threadIdx.x == 0) g_mask_is_i32 = (any == 0) ? 1 : 0;
}

// ---------------------------------------------------------------------------
// Mask -> fragment-layout bitwords. Grid 2048 blocks (b,qt,kt), 256 threads.
// Thread tid's word packs bits (nt*4+j): row = w*16+(l>>2)+(j>>1)*8,
// col = 2*(l&3) + nt*8 + (j&1) within the (128 x 64) tile.
// ---------------------------------------------------------------------------
__global__ void __launch_bounds__(256)
convert_mask_frag(const void* __restrict__ raw, uint32_t* __restrict__ out) {
    __shared__ unsigned char mt[128 * 64];
    const int blk = blockIdx.x;
    const int kt = blk & 31, qt = (blk >> 5) & 15, b = blk >> 9;
    const int tid = threadIdx.x;
    const size_t base = ((size_t)b * S_LEN + qt * 128) * S_LEN + kt * 64;

    if (g_mask_is_i32) {
        const int* m = (const int*)raw;
#pragma unroll
        for (int i = 0; i < 8; i++) {
            const int c = tid + i * 256;              // 0..2047 int4 chunks
            const int row = c >> 4, c4 = (c & 15) * 4;
            const int4 v = *(const int4*)(m + base + (size_t)row * S_LEN + c4);
            mt[row * 64 + c4 + 0] = (unsigned char)v.x;
            mt[row * 64 + c4 + 1] = (unsigned char)v.y;
            mt[row * 64 + c4 + 2] = (unsigned char)v.z;
            mt[row * 64 + c4 + 3] = (unsigned char)v.w;
        }
    } else {
        const unsigned char* m = (const unsigned char*)raw;
#pragma unroll
        for (int i = 0; i < 2; i++) {
            const int c = tid + i * 256;              // 0..511 16B chunks
            const int row = c >> 2, col = (c & 3) * 16;
            *(uint4*)&mt[row * 64 + col] =
                *(const uint4*)(m + base + (size_t)row * S_LEN + col);
        }
    }
    __syncthreads();

    const int w = tid >> 5, l = tid & 31;
    const int r0 = w * 16 + (l >> 2);
    const int c0 = 2 * (l & 3);
    uint32_t word = 0;
#pragma unroll
    for (int nt = 0; nt < 8; nt++) {
#pragma unroll
        for (int j = 0; j < 4; j++) {
            const int r = r0 + ((j >> 1) ? 8 : 0);
            const int c = c0 + nt * 8 + (j & 1);
            word |= (mt[r * 64 + c] ? 1u : 0u) << (nt * 4 + j);
        }
    }
    out[(size_t)blk * 256 + tid] = word;
}

// ---------------------------------------------------------------------------
// Pack fp32 -> hi/lo bf16 (row-major flat)
// ---------------------------------------------------------------------------
__global__ void __launch_bounds__(256)
pack_hilo(const float* __restrict__ src, __nv_bfloat16* __restrict__ hi,
          __nv_bfloat16* __restrict__ lo) {
    const size_t idx = (size_t)blockIdx.x * 256 + threadIdx.x;
    const float4 v = *(const float4*)(src + idx * 4);
    uint32_t h0, l0, h1, l1;
    split_hilo(v.x, v.y, h0, l0);
    split_hilo(v.z, v.w, h1, l1);
    *(uint2*)(hi + idx * 4) = make_uint2(h0, h1);
    *(uint2*)(lo + idx * 4) = make_uint2(l0, l1);
}

// ---------------------------------------------------------------------------
// bf16 hi/lo GEMM via mma.sync — now 2 CTAs/SM for cross-CTA pipe overlap
// ---------------------------------------------------------------------------
#define GP 80
#define GT_TILE (128 * GP)
#define GT_STAGE (4 * GT_TILE)
#define GT_SMEM (2 * GT_STAGE)     // 81920 B/CTA -> 2 CTAs = 160 KB/SM

__global__ void __launch_bounds__(256, 2)
gemm_mma(const __nv_bfloat16* __restrict__ Ahi, const __nv_bfloat16* __restrict__ Alo,
         const __nv_bfloat16* __restrict__ Bhi, const __nv_bfloat16* __restrict__ Blo,
         const float* __restrict__ bias, float* __restrict__ C, int n_dim, int epi_mode,
         __nv_bfloat16* qh, __nv_bfloat16* ql, __nv_bfloat16* kh,
         __nv_bfloat16* kl, __nv_bfloat16* vh, __nv_bfloat16* vl) {
    extern __shared__ __align__(1024) char smem[];
    const uint32_t sb = smem_to_u32(smem);
    const int tid = threadIdx.x;
    const int bx = blockIdx.x, by = blockIdx.y;
    const int w = tid >> 5, l = tid & 31;
    const int wm = w >> 1, wn = w & 1;

    const int c0row = tid >> 2,        c0col = tid & 3;
    const int c1row = (tid + 256) >> 2, c1col = (tid + 256) & 3;

    const __nv_bfloat16* srcs[4] = {Ahi, Alo, Bhi, Blo};
    const size_t rowbase[4] = {(size_t)by * 128, (size_t)by * 128,
                               (size_t)bx * 128, (size_t)bx * 128};

    float acc[2][8][4];
#pragma unroll
    for (int i = 0; i < 2; i++)
#pragma unroll
        for (int j = 0; j < 8; j++)
#pragma unroll
            for (int q = 0; q < 4; q++) acc[i][j][q] = 0.0f;

    const uint32_t a_lane = (uint32_t)(l & 15) * GP + ((l >> 4) & 1) * 16;
    const uint32_t b_lane = (uint32_t)((l & 7) + ((l >> 4) & 1) * 8) * GP + ((l >> 3) & 1) * 16;

    auto issue = [&](int s, int k0) {
        const uint32_t st = sb + s * GT_STAGE;
#pragma unroll
        for (int t = 0; t < 4; t++) {
            const __nv_bfloat16* base = srcs[t] + (rowbase[t]) * GK + k0;
            cp_async16(st + t * GT_TILE + c0row * GP + c0col * 16,
                       base + (size_t)c0row * GK + c0col * 8);
            cp_async16(st + t * GT_TILE + c1row * GP + c1col * 16,
                       base + (size_t)c1row * GK + c1col * 8);
        }
        CP_COMMIT();
    };

    issue(0, 0);

    for (int kt = 0; kt < GK / 32; kt++) {
        const int s = kt & 1;
        CP_WAIT0();
        __syncthreads();
        if (kt + 1 < GK / 32) issue(s ^ 1, (kt + 1) * 32);

        const uint32_t st = sb + s * GT_STAGE;
#pragma unroll
        for (int ks = 0; ks < 2; ks++) {
            const uint32_t kb = ks * 32;
            uint32_t ah[2][4], al[2][4], bh2[4][4], bl2[4][4];
#pragma unroll
            for (int mi = 0; mi < 2; mi++) {
                const uint32_t ao = (uint32_t)(wm * 32 + mi * 16) * GP + kb + a_lane;
                ldmx4(ah[mi], st + ao);
                ldmx4(al[mi], st + GT_TILE + ao);
            }
#pragma unroll
            for (int bi = 0; bi < 4; bi++) {
                const uint32_t bo = (uint32_t)(wn * 64 + bi * 16) * GP + kb + b_lane;
                ldmx4(bh2[bi], st + 2 * GT_TILE + bo);
                ldmx4(bl2[bi], st + 3 * GT_TILE + bo);
            }
#pragma unroll
            for (int mi = 0; mi < 2; mi++)
#pragma unroll
                for (int bi = 0; bi < 4; bi++)
#pragma unroll
                    for (int t = 0; t < 2; t++) {
                        float* c = acc[mi][bi * 2 + t];
                        mma16816(c, ah[mi], bh2[bi][t * 2], bh2[bi][t * 2 + 1]);
                        mma16816(c, al[mi], bh2[bi][t * 2], bh2[bi][t * 2 + 1]);
                        mma16816(c, ah[mi], bl2[bi][t * 2], bl2[bi][t * 2 + 1]);
                    }
        }
        __syncthreads();
    }

    const int mg = by * 128 + wm * 32 + (l >> 2);
    const int ng0 = bx * 128 + wn * 64 + (l & 3) * 2;

    if (epi_mode == 0) {
#pragma unroll
        for (int mi = 0; mi < 2; mi++) {
#pragma unroll
            for (int ni = 0; ni < 8; ni++) {
                const int n = ng0 + ni * 8;
                const float2 bv = *(const float2*)(bias + n);
                const int m0 = mg + mi * 16;
                *(float2*)(C + (size_t)m0 * n_dim + n) =
                    make_float2(acc[mi][ni][0] + bv.x, acc[mi][ni][1] + bv.y);
                *(float2*)(C + (size_t)(m0 + 8) * n_dim + n) =
                    make_float2(acc[mi][ni][2] + bv.x, acc[mi][ni][3] + bv.y);
            }
        }
    } else {
#pragma unroll
        for (int mi = 0; mi < 2; mi++) {
#pragma unroll
            for (int ni = 0; ni < 8; ni++) {
                const int n = ng0 + ni * 8;
                const int hh = n / 192;
                const int r = n - hh * 192;
                const int kind = r >> 6;
                const int d = r & 63;
                const float b0 = bias[n], b1 = bias[n + 1];
                __nv_bfloat16* dsth = (kind == 0) ? qh : (kind == 1) ? kh : vh;
                __nv_bfloat16* dstl = (kind == 0) ? ql : (kind == 1) ? kl : vl;
#pragma unroll
                for (int hf = 0; hf < 2; hf++) {
                    const int m = mg + mi * 16 + hf * 8;
                    const int s = m >> 2, bb = m & 3;
                    const size_t off = ((size_t)(bb * NHEADS + hh) * S_LEN + s) * 64 + d;
                    uint32_t hiw, low;
                    split_hilo(acc[mi][ni][hf * 2 + 0] + b0,
                               acc[mi][ni][hf * 2 + 1] + b1, hiw, low);
                    *(uint32_t*)(dsth + off) = hiw;
                    *(uint32_t*)(dstl + off) = low;
                }
            }
        }
    }
}

// ---------------------------------------------------------------------------
// Tensor-core flash attention v4: 3-stage pipeline, ONE sync per iteration,
// fragment-layout bitmask (no mask in smem). K-tile 64, 2 CTAs/SM.
// ---------------------------------------------------------------------------
#define A_ARR (64 * 144)                  // 9216 B per array
#define A_STAGE (4 * A_ARR)               // 36864 B (Kh,Kl,Vh,Vl)
#define A_SMEM (3 * A_STAGE)              // 110592 B -> 2 CTAs/SM

__global__ void __launch_bounds__(256, 2)
attention_mma(const uint32_t* __restrict__ maskw,
              const __nv_bfloat16* __restrict__ Qh, const __nv_bfloat16* __restrict__ Ql,
              const __nv_bfloat16* __restrict__ Kh, const __nv_bfloat16* __restrict__ Kl,
              const __nv_bfloat16* __restrict__ Vh, const __nv_bfloat16* __restrict__ Vl,
              __nv_bfloat16* __restrict__ ctxh, __nv_bfloat16* __restrict__ ctxl) {
    extern __shared__ __align__(1024) char smem[];
    const uint32_t sb = smem_to_u32(smem);
    const int tid = threadIdx.x, w = tid >> 5, l = tid & 31;
    const int qt = blockIdx.x, bh = blockIdx.y;
    const int b = bh >> 4, h = bh & 15;
    const int q0 = qt * 128;
    const uint32_t* mrow_base = maskw + (size_t)((b << 9) | (qt << 5)) * 256 + tid;

    // Q fragments straight from gmem
    uint32_t qfh[4][4], qfl[4][4];
    {
        const __nv_bfloat16* qgh = Qh + ((size_t)bh * S_LEN + q0 + w * 16) * 64;
        const __nv_bfloat16* qgl = Ql + ((size_t)bh * S_LEN + q0 + w * 16) * 64;
        const int r0 = l >> 2, k0 = 2 * (l & 3);
#pragma unroll
        for (int ks = 0; ks < 4; ks++) {
            const int kk = ks * 16 + k0;
            qfh[ks][0] = *(const uint32_t*)(qgh + r0 * 64 + kk);
            qfh[ks][1] = *(const uint32_t*)(qgh + (r0 + 8) * 64 + kk);
            qfh[ks][2] = *(const uint32_t*)(qgh + r0 * 64 + kk + 8);
            qfh[ks][3] = *(const uint32_t*)(qgh + (r0 + 8) * 64 + kk + 8);
            qfl[ks][0] = *(const uint32_t*)(qgl + r0 * 64 + kk);
            qfl[ks][1] = *(const uint32_t*)(qgl + (r0 + 8) * 64 + kk);
            qfl[ks][2] = *(const uint32_t*)(qgl + r0 * 64 + kk + 8);
            qfl[ks][3] = *(const uint32_t*)(qgl + (r0 + 8) * 64 + kk + 8);
        }
    }

    float acc[8][4];
#pragma unroll
    for (int i = 0; i < 8; i++)
#pragma unroll
        for (int j = 0; j < 4; j++) acc[i][j] = 0.0f;
    float m0 = -1e30f, m1 = -1e30f, lsum0 = 0.0f, lsum1 = 0.0f;

    auto issue = [&](int kt) {
        const uint32_t st = sb + (uint32_t)(kt % 3) * A_STAGE;
        const __nv_bfloat16* arrs[4] = {Kh, Kl, Vh, Vl};
#pragma unroll
        for (int i = 0; i < 8; i++) {
            const int c = tid + i * 256;
            const int arr = c >> 9;
            const int cc = c & 511;
            const int row = cc >> 3, col = cc & 7;
            cp_async16(st + arr * A_ARR + row * 144 + col * 16,
                       arrs[arr] + ((size_t)bh * S_LEN + kt * 64 + row) * 64 + col * 8);
        }
        CP_COMMIT();
    };

    issue(0);
    issue(1);

    const uint32_t klane = (uint32_t)((l & 7) + ((l >> 4) & 1) * 8) * 144 + ((l >> 3) & 1) * 16;
    const uint32_t vlane = (uint32_t)((l & 7) + ((l >> 3) & 1) * 8) * 144 + ((l >> 4) & 1) * 16;

    for (int kt = 0; kt < 32; kt++) {
        if (kt == 31) { CP_WAIT0(); } else { CP_WAIT1(); }
        __syncthreads();
        if (kt + 2 < 32) issue(kt + 2);

        const uint32_t st = sb + (uint32_t)(kt % 3) * A_STAGE;
        const uint32_t mw = mrow_base[(size_t)kt * 256];   // 32 mask bits

        // ---- scores = Q K^T (hi/lo, 3 terms) ----
        float sc[8][4];
#pragma unroll
        for (int i = 0; i < 8; i++) { sc[i][0] = sc[i][1] = sc[i][2] = sc[i][3] = 0.0f; }
#pragma unroll
        for (int ks = 0; ks < 4; ks++) {
#pragma unroll
            for (int nt2 = 0; nt2 < 4; nt2++) {
                uint32_t kh4[4], kl4[4];
                const uint32_t ao = st + (uint32_t)(nt2 * 16) * 144 + ks * 32 + klane;
                ldmx4(kh4, ao);
                ldmx4(kl4, ao + A_ARR);
                mma16816(sc[2 * nt2],     qfh[ks], kh4[0], kh4[1]);
                mma16816(sc[2 * nt2],     qfl[ks], kh4[0], kh4[1]);
                mma16816(sc[2 * nt2],     qfh[ks], kl4[0], kl4[1]);
                mma16816(sc[2 * nt2 + 1], qfh[ks], kh4[2], kh4[3]);
                mma16816(sc[2 * nt2 + 1], qfl[ks], kh4[2], kh4[3]);
                mma16816(sc[2 * nt2 + 1], qfh[ks], kl4[2], kl4[3]);
            }
        }

        // ---- scale + mask via bitword (log2 domain) ----
#pragma unroll
        for (int nt = 0; nt < 8; nt++) {
            sc[nt][0] = (mw >> (nt * 4 + 0)) & 1 ? MASK_L2 : sc[nt][0] * SCALE_L2E;
            sc[nt][1] = (mw >> (nt * 4 + 1)) & 1 ? MASK_L2 : sc[nt][1] * SCALE_L2E;
            sc[nt][2] = (mw >> (nt * 4 + 2)) & 1 ? MASK_L2 : sc[nt][2] * SCALE_L2E;
            sc[nt][3] = (mw >> (nt * 4 + 3)) & 1 ? MASK_L2 : sc[nt][3] * SCALE_L2E;
        }

        // ---- online softmax (log2 domain, ex2 on MUFU) ----
        float mx0 = sc[0][0], mx1 = sc[0][2];
#pragma unroll
        for (int nt = 0; nt < 8; nt++) {
            mx0 = fmaxf(mx0, fmaxf(sc[nt][0], sc[nt][1]));
            mx1 = fmaxf(mx1, fmaxf(sc[nt][2], sc[nt][3]));
        }
        mx0 = fmaxf(mx0, __shfl_xor_sync(0xFFFFFFFFu, mx0, 1));
        mx0 = fmaxf(mx0, __shfl_xor_sync(0xFFFFFFFFu, mx0, 2));
        mx1 = fmaxf(mx1, __shfl_xor_sync(0xFFFFFFFFu, mx1, 1));
        mx1 = fmaxf(mx1, __shfl_xor_sync(0xFFFFFFFFu, mx1, 2));

        const float nm0 = fmaxf(m0, mx0), nm1 = fmaxf(m1, mx1);
        const float cr0 = ex2(m0 - nm0), cr1 = ex2(m1 - nm1);
        m0 = nm0; m1 = nm1;

        float s0 = 0.0f, s1 = 0.0f;
#pragma unroll
        for (int nt = 0; nt < 8; nt++) {
            sc[nt][0] = ex2(sc[nt][0] - nm0); s0 += sc[nt][0];
            sc[nt][1] = ex2(sc[nt][1] - nm0); s0 += sc[nt][1];
            sc[nt][2] = ex2(sc[nt][2] - nm1); s1 += sc[nt][2];
            sc[nt][3] = ex2(sc[nt][3] - nm1); s1 += sc[nt][3];
        }
        s0 += __shfl_xor_sync(0xFFFFFFFFu, s0, 1);
        s0 += __shfl_xor_sync(0xFFFFFFFFu, s0, 2);
        s1 += __shfl_xor_sync(0xFFFFFFFFu, s1, 1);
        s1 += __shfl_xor_sync(0xFFFFFFFFu, s1, 2);
        lsum0 = lsum0 * cr0 + s0;
        lsum1 = lsum1 * cr1 + s1;
#pragma unroll
        for (int nt = 0; nt < 8; nt++) {
            acc[nt][0] *= cr0; acc[nt][1] *= cr0;
            acc[nt][2] *= cr1; acc[nt][3] *= cr1;
        }

        // ---- ctx += P V (hi/lo, 3 terms) ----
#pragma unroll
        for (int kt16 = 0; kt16 < 4; kt16++) {
            uint32_t ph[4], pl[4];
            split_hilo(sc[2 * kt16][0],     sc[2 * kt16][1],     ph[0], pl[0]);
            split_hilo(sc[2 * kt16][2],     sc[2 * kt16][3],     ph[1], pl[1]);
            split_hilo(sc[2 * kt16 + 1][0], sc[2 * kt16 + 1][1], ph[2], pl[2]);
            split_hilo(sc[2 * kt16 + 1][2], sc[2 * kt16 + 1][3], ph[3], pl[3]);
#pragma unroll
            for (int db = 0; db < 4; db++) {
                uint32_t vh4[4], vl4[4];
                const uint32_t ao = st + 2 * A_ARR + (uint32_t)(kt16 * 16) * 144 + db * 32 + vlane;
                ldmx4t(vh4, ao);
                ldmx4t(vl4, ao + A_ARR);
                mma16816(acc[2 * db],     ph, vh4[0], vh4[1]);
                mma16816(acc[2 * db],     pl, vh4[0], vh4[1]);
                mma16816(acc[2 * db],     ph, vl4[0], vl4[1]);
                mma16816(acc[2 * db + 1], ph, vh4[2], vh4[3]);
                mma16816(acc[2 * db + 1], pl, vh4[2], vh4[3]);
                mma16816(acc[2 * db + 1], ph, vl4[2], vl4[3]);
            }
        }
        // no trailing sync: single barrier per iter is sufficient with 3 stages
    }

    // ---- normalize + write ctx as bf16 hi/lo ----
    const float i0 = 1.0f / lsum0, i1 = 1.0f / lsum1;
    const int srow = q0 + w * 16 + (l >> 2);
    const int colb = h * 64 + 2 * (l & 3);
#pragma unroll
    for (int nt = 0; nt < 8; nt++) {
        const int col = colb + nt * 8;
        uint32_t hiw, low;
        split_hilo(acc[nt][0] * i0, acc[nt][1] * i0, hiw, low);
        const size_t off0 = ((size_t)srow * 4 + b) * HID + col;
        *(uint32_t*)(ctxh + off0) = hiw;
        *(uint32_t*)(ctxl + off0) = low;
        split_hilo(acc[nt][2] * i1, acc[nt][3] * i1, hiw, low);
        const size_t off1 = ((size_t)(srow + 8) * 4 + b) * HID + col;
        *(uint32_t*)(ctxh + off1) = hiw;
        *(uint32_t*)(ctxl + off1) = low;
    }
}

// ---------------------------------------------------------------------------
// Launch
// ---------------------------------------------------------------------------
extern "C" void kernel_launch(void* const* d_in, const int* in_sizes, int n_in,
                              void* d_out, int out_size) {
    const float* hs      = (const float*)d_in[0];
    const void*  mask    = d_in[1];
    const float* W_qkv   = (const float*)d_in[2];
    const float* b_qkv   = (const float*)d_in[3];
    const float* W_dense = (const float*)d_in[4];
    const float* b_dense = (const float*)d_in[5];
    float* out = (float*)d_out;

    __nv_bfloat16 *pAh, *pAl, *pWqh, *pWql, *pWdh, *pWdl;
    __nv_bfloat16 *Qh, *Ql, *Kh, *Kl, *Vh, *Vl;
    uint32_t* maskbits;
    cudaGetSymbolAddress((void**)&pAh, g_pA_hi);
    cudaGetSymbolAddress((void**)&pAl, g_pA_lo);
    cudaGetSymbolAddress((void**)&pWqh, g_pWq_hi);
    cudaGetSymbolAddress((void**)&pWql, g_pWq_lo);
    cudaGetSymbolAddress((void**)&pWdh, g_pWd_hi);
    cudaGetSymbolAddress((void**)&pWdl, g_pWd_lo);
    cudaGetSymbolAddress((void**)&Qh, g_Qh);
    cudaGetSymbolAddress((void**)&Ql, g_Ql);
    cudaGetSymbolAddress((void**)&Kh, g_Kh);
    cudaGetSymbolAddress((void**)&Kl, g_Kl);
    cudaGetSymbolAddress((void**)&Vh, g_Vh);
    cudaGetSymbolAddress((void**)&Vl, g_Vl);
    cudaGetSymbolAddress((void**)&maskbits, g_mask_bits);

    cudaFuncSetAttribute(gemm_mma, cudaFuncAttributeMaxDynamicSharedMemorySize, GT_SMEM);
    cudaFuncSetAttribute(attention_mma, cudaFuncAttributeMaxDynamicSharedMemorySize, A_SMEM);

    // 0) mask dtype + fragment-layout bit conversion
    detect_mask_dtype<<<1, 32>>>((const int*)mask);
    convert_mask_frag<<<BATCH * 16 * 32, 256>>>(mask, maskbits);

    // 1) pack hs + W_qkv
    pack_hilo<<<(M_ROWS * HID / 4) / 256, 256>>>(hs, pAh, pAl);
    pack_hilo<<<(QKV_N * HID / 4) / 256, 256>>>(W_qkv, pWqh, pWql);

    // 2) QKV GEMM -> split bf16 hi/lo Q/K/V
    gemm_mma<<<dim3(QKV_N / 128, M_ROWS / 128), 256, GT_SMEM>>>(
        pAh, pAl, pWqh, pWql, b_qkv, nullptr, QKV_N, 1, Qh, Ql, Kh, Kl, Vh, Vl);

    // 3) tensor-core flash attention -> ctx hi/lo (into pA buffers)
    attention_mma<<<dim3(S_LEN / 128, BATCH * NHEADS), 256, A_SMEM>>>(
        maskbits, Qh, Ql, Kh, Kl, Vh, Vl, pAh, pAl);

    // 4) pack W_dense + dense GEMM -> out
    pack_hilo<<<(HID * HID / 4) / 256, 256>>>(W_dense, pWdh, pWdl);
    gemm_mma<<<dim3(HID / 128, M_ROWS / 128), 256, GT_SMEM>>>(
        pAh, pAl, pWdh, pWdl, b_dense, out, HID, 0,
        nullptr, nullptr, nullptr, nullptr, nullptr, nullptr);
}

// round 12
// speedup vs baseline: 9.3148x; 1.0085x over previous
#include <cuda_runtime.h>
#include <cuda_bf16.h>
#include <math.h>
#include <stdint.h>

#define S_LEN 2048
#define BATCH 4
#define HID 1024
#define NHEADS 16
#define HDIM 64
#define M_ROWS (S_LEN * BATCH)   // 8192
#define QKV_N (3 * HID)          // 3072
#define GK HID                   // K dim of both GEMMs = 1024
#define SCALE_L2E 0.18033688011112043f   // 0.125 * log2(e)
#define MASK_L2  (-14426.950408889634f)  // -10000 * log2(e)

// ---------------- scratch (allocation-free: device globals) ----------------
__device__ int g_mask_is_i32;
__device__ uint32_t g_mask_bits[(size_t)BATCH * 16 * 32 * 256];   // 2 MB

#define QKV_ELEMS ((size_t)64 * S_LEN * HDIM)
__device__ __align__(16) __nv_bfloat16 g_Qh[QKV_ELEMS], g_Ql[QKV_ELEMS];
__device__ __align__(16) __nv_bfloat16 g_Kh[QKV_ELEMS], g_Kl[QKV_ELEMS];
__device__ __align__(16) __nv_bfloat16 g_Vh[QKV_ELEMS], g_Vl[QKV_ELEMS];

__device__ __align__(16) __nv_bfloat16 g_pA_hi[(size_t)M_ROWS * HID];
__device__ __align__(16) __nv_bfloat16 g_pA_lo[(size_t)M_ROWS * HID];
__device__ __align__(16) __nv_bfloat16 g_pWq_hi[(size_t)QKV_N * HID];
__device__ __align__(16) __nv_bfloat16 g_pWq_lo[(size_t)QKV_N * HID];
__device__ __align__(16) __nv_bfloat16 g_pWd_hi[(size_t)HID * HID];
__device__ __align__(16) __nv_bfloat16 g_pWd_lo[(size_t)HID * HID];

// ---------------- helpers ----------------
__device__ __forceinline__ uint32_t smem_to_u32(const void* p) {
    uint32_t a;
    asm("{ .reg .u64 t; cvta.to.shared.u64 t, %1; cvt.u32.u64 %0, t; }" : "=r"(a) : "l"(p));
    return a;
}
__device__ __forceinline__ void cp_async16(uint32_t dst, const void* src) {
    asm volatile("cp.async.cg.shared.global [%0], [%1], 16;" :: "r"(dst), "l"(src));
}
#define CP_COMMIT() asm volatile("cp.async.commit_group;" ::: "memory")
#define CP_WAIT0()  asm volatile("cp.async.wait_group 0;" ::: "memory")
#define CP_WAIT1()  asm volatile("cp.async.wait_group 1;" ::: "memory")

__device__ __forceinline__ void ldmx4(uint32_t* r, uint32_t addr) {
    asm volatile("ldmatrix.sync.aligned.m8n8.x4.shared.b16 {%0,%1,%2,%3}, [%4];"
                 : "=r"(r[0]), "=r"(r[1]), "=r"(r[2]), "=r"(r[3]) : "r"(addr));
}
__device__ __forceinline__ void ldmx4t(uint32_t* r, uint32_t addr) {
    asm volatile("ldmatrix.sync.aligned.m8n8.x4.trans.shared.b16 {%0,%1,%2,%3}, [%4];"
                 : "=r"(r[0]), "=r"(r[1]), "=r"(r[2]), "=r"(r[3]) : "r"(addr));
}
__device__ __forceinline__ void mma16816(float* c, const uint32_t* a, uint32_t b0, uint32_t b1) {
    asm volatile(
        "mma.sync.aligned.m16n8k16.row.col.f32.bf16.bf16.f32 "
        "{%0,%1,%2,%3}, {%4,%5,%6,%7}, {%8,%9}, {%0,%1,%2,%3};"
        : "+f"(c[0]), "+f"(c[1]), "+f"(c[2]), "+f"(c[3])
        : "r"(a[0]), "r"(a[1]), "r"(a[2]), "r"(a[3]), "r"(b0), "r"(b1));
}
__device__ __forceinline__ uint32_t packbf2(float vhigh, float vlow) {
    uint32_t r;
    asm("cvt.rn.bf16x2.f32 %0, %1, %2;" : "=r"(r) : "f"(vhigh), "f"(vlow));
    return r;
}
__device__ __forceinline__ void split_hilo(float v0, float v1, uint32_t& hi, uint32_t& lo) {
    hi = packbf2(v1, v0);
    const float h0 = __int_as_float(hi << 16);
    const float h1 = __int_as_float(hi & 0xFFFF0000u);
    lo = packbf2(v1 - h1, v0 - h0);
}
__device__ __forceinline__ float ex2(float x) {
    float y;
    asm("ex2.approx.f32 %0, %1;" : "=f"(y) : "f"(x));
    return y;
}

// ---------------------------------------------------------------------------
// Mask dtype detect
// ---------------------------------------------------------------------------
__global__ void detect_mask_dtype(const int* __restrict__ m) {
    int bad = 0;
#pragma unroll
    for (int i = 0; i < 32; i++) {
        unsigned v = (unsigned)m[threadIdx.x * 32 + i];
        bad |= (v > 1u);
    }
    unsigned any = __ballot_sync(0xFFFFFFFFu, bad);
    if (threadIdx.x == 0) g_mask_is_i32 = (any == 0) ? 1 : 0;
}

// ---------------------------------------------------------------------------
// Mask -> fragment-layout bitwords (verified in R11)
// ---------------------------------------------------------------------------
__global__ void __launch_bounds__(256)
convert_mask_frag(const void* __restrict__ raw, uint32_t* __restrict__ out) {
    __shared__ unsigned char mt[128 * 64];
    const int blk = blockIdx.x;
    const int kt = blk & 31, qt = (blk >> 5) & 15, b = blk >> 9;
    const int tid = threadIdx.x;
    const size_t base = ((size_t)b * S_LEN + qt * 128) * S_LEN + kt * 64;

    if (g_mask_is_i32) {
        const int* m = (const int*)raw;
#pragma unroll
        for (int i = 0; i < 8; i++) {
            const int c = tid + i * 256;
            const int row = c >> 4, c4 = (c & 15) * 4;
            const int4 v = *(const int4*)(m + base + (size_t)row * S_LEN + c4);
            mt[row * 64 + c4 + 0] = (unsigned char)v.x;
            mt[row * 64 + c4 + 1] = (unsigned char)v.y;
            mt[row * 64 + c4 + 2] = (unsigned char)v.z;
            mt[row * 64 + c4 + 3] = (unsigned char)v.w;
        }
    } else {
        const unsigned char* m = (const unsigned char*)raw;
#pragma unroll
        for (int i = 0; i < 2; i++) {
            const int c = tid + i * 256;
            const int row = c >> 2, col = (c & 3) * 16;
            *(uint4*)&mt[row * 64 + col] =
                *(const uint4*)(m + base + (size_t)row * S_LEN + col);
        }
    }
    __syncthreads();

    const int w = tid >> 5, l = tid & 31;
    const int r0 = w * 16 + (l >> 2);
    const int c0 = 2 * (l & 3);
    uint32_t word = 0;
#pragma unroll
    for (int nt = 0; nt < 8; nt++) {
#pragma unroll
        for (int j = 0; j < 4; j++) {
            const int r = r0 + ((j >> 1) ? 8 : 0);
            const int c = c0 + nt * 8 + (j & 1);
            word |= (mt[r * 64 + c] ? 1u : 0u) << (nt * 4 + j);
        }
    }
    out[(size_t)blk * 256 + tid] = word;
}

// ---------------------------------------------------------------------------
// Pack fp32 -> hi/lo bf16 (row-major flat)
// ---------------------------------------------------------------------------
__global__ void __launch_bounds__(256)
pack_hilo(const float* __restrict__ src, __nv_bfloat16* __restrict__ hi,
          __nv_bfloat16* __restrict__ lo) {
    const size_t idx = (size_t)blockIdx.x * 256 + threadIdx.x;
    const float4 v = *(const float4*)(src + idx * 4);
    uint32_t h0, l0, h1, l1;
    split_hilo(v.x, v.y, h0, l0);
    split_hilo(v.z, v.w, h1, l1);
    *(uint2*)(hi + idx * 4) = make_uint2(h0, h1);
    *(uint2*)(lo + idx * 4) = make_uint2(l0, l1);
}

// ---------------------------------------------------------------------------
// bf16 hi/lo GEMM via mma.sync — 2 CTAs/SM, ONE sync per iter
// ---------------------------------------------------------------------------
#define GP 80
#define GT_TILE (128 * GP)
#define GT_STAGE (4 * GT_TILE)
#define GT_SMEM (2 * GT_STAGE)     // 81920 B/CTA -> 2 CTAs = 160 KB/SM

__global__ void __launch_bounds__(256, 2)
gemm_mma(const __nv_bfloat16* __restrict__ Ahi, const __nv_bfloat16* __restrict__ Alo,
         const __nv_bfloat16* __restrict__ Bhi, const __nv_bfloat16* __restrict__ Blo,
         const float* __restrict__ bias, float* __restrict__ C, int n_dim, int epi_mode,
         __nv_bfloat16* qh, __nv_bfloat16* ql, __nv_bfloat16* kh,
         __nv_bfloat16* kl, __nv_bfloat16* vh, __nv_bfloat16* vl) {
    extern __shared__ __align__(1024) char smem[];
    const uint32_t sb = smem_to_u32(smem);
    const int tid = threadIdx.x;
    const int bx = blockIdx.x, by = blockIdx.y;
    const int w = tid >> 5, l = tid & 31;
    const int wm = w >> 1, wn = w & 1;

    const int c0row = tid >> 2,        c0col = tid & 3;
    const int c1row = (tid + 256) >> 2, c1col = (tid + 256) & 3;

    const __nv_bfloat16* srcs[4] = {Ahi, Alo, Bhi, Blo};
    const size_t rowbase[4] = {(size_t)by * 128, (size_t)by * 128,
                               (size_t)bx * 128, (size_t)bx * 128};

    float acc[2][8][4];
#pragma unroll
    for (int i = 0; i < 2; i++)
#pragma unroll
        for (int j = 0; j < 8; j++)
#pragma unroll
            for (int q = 0; q < 4; q++) acc[i][j][q] = 0.0f;

    const uint32_t a_lane = (uint32_t)(l & 15) * GP + ((l >> 4) & 1) * 16;
    const uint32_t b_lane = (uint32_t)((l & 7) + ((l >> 4) & 1) * 8) * GP + ((l >> 3) & 1) * 16;

    auto issue = [&](int s, int k0) {
        const uint32_t st = sb + s * GT_STAGE;
#pragma unroll
        for (int t = 0; t < 4; t++) {
            const __nv_bfloat16* base = srcs[t] + (rowbase[t]) * GK + k0;
            cp_async16(st + t * GT_TILE + c0row * GP + c0col * 16,
                       base + (size_t)c0row * GK + c0col * 8);
            cp_async16(st + t * GT_TILE + c1row * GP + c1col * 16,
                       base + (size_t)c1row * GK + c1col * 8);
        }
        CP_COMMIT();
    };

    issue(0, 0);

    for (int kt = 0; kt < GK / 32; kt++) {
        const int s = kt & 1;
        CP_WAIT0();
        __syncthreads();      // single barrier: also protects next issue's overwrite
        if (kt + 1 < GK / 32) issue(s ^ 1, (kt + 1) * 32);

        const uint32_t st = sb + s * GT_STAGE;
#pragma unroll
        for (int ks = 0; ks < 2; ks++) {
            const uint32_t kb = ks * 32;
            uint32_t ah[2][4], al[2][4], bh2[4][4], bl2[4][4];
#pragma unroll
            for (int mi = 0; mi < 2; mi++) {
                const uint32_t ao = (uint32_t)(wm * 32 + mi * 16) * GP + kb + a_lane;
                ldmx4(ah[mi], st + ao);
                ldmx4(al[mi], st + GT_TILE + ao);
            }
#pragma unroll
            for (int bi = 0; bi < 4; bi++) {
                const uint32_t bo = (uint32_t)(wn * 64 + bi * 16) * GP + kb + b_lane;
                ldmx4(bh2[bi], st + 2 * GT_TILE + bo);
                ldmx4(bl2[bi], st + 3 * GT_TILE + bo);
            }
#pragma unroll
            for (int mi = 0; mi < 2; mi++)
#pragma unroll
                for (int bi = 0; bi < 4; bi++)
#pragma unroll
                    for (int t = 0; t < 2; t++) {
                        float* c = acc[mi][bi * 2 + t];
                        mma16816(c, ah[mi], bh2[bi][t * 2], bh2[bi][t * 2 + 1]);
                        mma16816(c, al[mi], bh2[bi][t * 2], bh2[bi][t * 2 + 1]);
                        mma16816(c, ah[mi], bl2[bi][t * 2], bl2[bi][t * 2 + 1]);
                    }
        }
        // no trailing sync (top barrier of next iter provides safety)
    }

    const int mg = by * 128 + wm * 32 + (l >> 2);
    const int ng0 = bx * 128 + wn * 64 + (l & 3) * 2;

    if (epi_mode == 0) {
#pragma unroll
        for (int mi = 0; mi < 2; mi++) {
#pragma unroll
            for (int ni = 0; ni < 8; ni++) {
                const int n = ng0 + ni * 8;
                const float2 bv = *(const float2*)(bias + n);
                const int m0 = mg + mi * 16;
                *(float2*)(C + (size_t)m0 * n_dim + n) =
                    make_float2(acc[mi][ni][0] + bv.x, acc[mi][ni][1] + bv.y);
                *(float2*)(C + (size_t)(m0 + 8) * n_dim + n) =
                    make_float2(acc[mi][ni][2] + bv.x, acc[mi][ni][3] + bv.y);
            }
        }
    } else {
#pragma unroll
        for (int mi = 0; mi < 2; mi++) {
#pragma unroll
            for (int ni = 0; ni < 8; ni++) {
                const int n = ng0 + ni * 8;
                const int hh = n / 192;
                const int r = n - hh * 192;
                const int kind = r >> 6;
                const int d = r & 63;
                const float b0 = bias[n], b1 = bias[n + 1];
                __nv_bfloat16* dsth = (kind == 0) ? qh : (kind == 1) ? kh : vh;
                __nv_bfloat16* dstl = (kind == 0) ? ql : (kind == 1) ? kl : vl;
#pragma unroll
                for (int hf = 0; hf < 2; hf++) {
                    const int m = mg + mi * 16 + hf * 8;
                    const int s = m >> 2, bb = m & 3;
                    const size_t off = ((size_t)(bb * NHEADS + hh) * S_LEN + s) * 64 + d;
                    uint32_t hiw, low;
                    split_hilo(acc[mi][ni][hf * 2 + 0] + b0,
                               acc[mi][ni][hf * 2 + 1] + b1, hiw, low);
                    *(uint32_t*)(dsth + off) = hiw;
                    *(uint32_t*)(dstl + off) = low;
                }
            }
        }
    }
}

// ---------------------------------------------------------------------------
// Tensor-core flash attention v5: software-pipelined inner loops (LDSM for
// step i+1 issued before MMAs of step i — asm volatile preserves order).
// 3-stage cp.async pipeline, one sync/iter, bitmask, 2 CTAs/SM.
// ---------------------------------------------------------------------------
#define A_ARR (64 * 144)                  // 9216 B per array
#define A_STAGE (4 * A_ARR)               // 36864 B (Kh,Kl,Vh,Vl)
#define A_SMEM (3 * A_STAGE)              // 110592 B -> 2 CTAs/SM

__global__ void __launch_bounds__(256, 2)
attention_mma(const uint32_t* __restrict__ maskw,
              const __nv_bfloat16* __restrict__ Qh, const __nv_bfloat16* __restrict__ Ql,
              const __nv_bfloat16* __restrict__ Kh, const __nv_bfloat16* __restrict__ Kl,
              const __nv_bfloat16* __restrict__ Vh, const __nv_bfloat16* __restrict__ Vl,
              __nv_bfloat16* __restrict__ ctxh, __nv_bfloat16* __restrict__ ctxl) {
    extern __shared__ __align__(1024) char smem[];
    const uint32_t sb = smem_to_u32(smem);
    const int tid = threadIdx.x, w = tid >> 5, l = tid & 31;
    const int qt = blockIdx.x, bh = blockIdx.y;
    const int b = bh >> 4, h = bh & 15;
    const int q0 = qt * 128;
    const uint32_t* mrow_base = maskw + (size_t)((b << 9) | (qt << 5)) * 256 + tid;

    // Q fragments straight from gmem
    uint32_t qfh[4][4], qfl[4][4];
    {
        const __nv_bfloat16* qgh = Qh + ((size_t)bh * S_LEN + q0 + w * 16) * 64;
        const __nv_bfloat16* qgl = Ql + ((size_t)bh * S_LEN + q0 + w * 16) * 64;
        const int r0 = l >> 2, k0 = 2 * (l & 3);
#pragma unroll
        for (int ks = 0; ks < 4; ks++) {
            const int kk = ks * 16 + k0;
            qfh[ks][0] = *(const uint32_t*)(qgh + r0 * 64 + kk);
            qfh[ks][1] = *(const uint32_t*)(qgh + (r0 + 8) * 64 + kk);
            qfh[ks][2] = *(const uint32_t*)(qgh + r0 * 64 + kk + 8);
            qfh[ks][3] = *(const uint32_t*)(qgh + (r0 + 8) * 64 + kk + 8);
            qfl[ks][0] = *(const uint32_t*)(qgl + r0 * 64 + kk);
            qfl[ks][1] = *(const uint32_t*)(qgl + (r0 + 8) * 64 + kk);
            qfl[ks][2] = *(const uint32_t*)(qgl + r0 * 64 + kk + 8);
            qfl[ks][3] = *(const uint32_t*)(qgl + (r0 + 8) * 64 + kk + 8);
        }
    }

    float acc[8][4];
#pragma unroll
    for (int i = 0; i < 8; i++)
#pragma unroll
        for (int j = 0; j < 4; j++) acc[i][j] = 0.0f;
    float m0 = -1e30f, m1 = -1e30f, lsum0 = 0.0f, lsum1 = 0.0f;

    auto issue = [&](int kt) {
        const uint32_t st = sb + (uint32_t)(kt % 3) * A_STAGE;
        const __nv_bfloat16* arrs[4] = {Kh, Kl, Vh, Vl};
#pragma unroll
        for (int i = 0; i < 8; i++) {
            const int c = tid + i * 256;
            const int arr = c >> 9;
            const int cc = c & 511;
            const int row = cc >> 3, col = cc & 7;
            cp_async16(st + arr * A_ARR + row * 144 + col * 16,
                       arrs[arr] + ((size_t)bh * S_LEN + kt * 64 + row) * 64 + col * 8);
        }
        CP_COMMIT();
    };

    issue(0);
    issue(1);

    const uint32_t klane = (uint32_t)((l & 7) + ((l >> 4) & 1) * 8) * 144 + ((l >> 3) & 1) * 16;
    const uint32_t vlane = (uint32_t)((l & 7) + ((l >> 3) & 1) * 8) * 144 + ((l >> 4) & 1) * 16;

    for (int kt = 0; kt < 32; kt++) {
        if (kt == 31) { CP_WAIT0(); } else { CP_WAIT1(); }
        __syncthreads();
        if (kt + 2 < 32) issue(kt + 2);

        const uint32_t st = sb + (uint32_t)(kt % 3) * A_STAGE;
        const uint32_t mw = mrow_base[(size_t)kt * 256];

        // ---- scores = Q K^T, software-pipelined (16 steps, ks-major) ----
        float sc[8][4];
#pragma unroll
        for (int i = 0; i < 8; i++) { sc[i][0] = sc[i][1] = sc[i][2] = sc[i][3] = 0.0f; }

        uint32_t kh4[2][4], kl4[2][4];
        {
            const uint32_t a0 = st + klane;          // step 0: ks=0, nt2=0
            ldmx4(kh4[0], a0);
            ldmx4(kl4[0], a0 + A_ARR);
        }
#pragma unroll
        for (int step = 0; step < 16; step++) {
            const int buf = step & 1;
            if (step < 15) {
                const int sn = step + 1;
                const uint32_t an = st + (uint32_t)((sn & 3) * 16) * 144 + (sn >> 2) * 32 + klane;
                ldmx4(kh4[buf ^ 1], an);
                ldmx4(kl4[buf ^ 1], an + A_ARR);
            }
            const int ks = step >> 2, nt2 = step & 3;
            mma16816(sc[2 * nt2],     qfh[ks], kh4[buf][0], kh4[buf][1]);
            mma16816(sc[2 * nt2],     qfl[ks], kh4[buf][0], kh4[buf][1]);
            mma16816(sc[2 * nt2],     qfh[ks], kl4[buf][0], kl4[buf][1]);
            mma16816(sc[2 * nt2 + 1], qfh[ks], kh4[buf][2], kh4[buf][3]);
            mma16816(sc[2 * nt2 + 1], qfl[ks], kh4[buf][2], kh4[buf][3]);
            mma16816(sc[2 * nt2 + 1], qfh[ks], kl4[buf][2], kl4[buf][3]);
        }

        // ---- scale + mask via bitword (log2 domain) ----
#pragma unroll
        for (int nt = 0; nt < 8; nt++) {
            sc[nt][0] = (mw >> (nt * 4 + 0)) & 1 ? MASK_L2 : sc[nt][0] * SCALE_L2E;
            sc[nt][1] = (mw >> (nt * 4 + 1)) & 1 ? MASK_L2 : sc[nt][1] * SCALE_L2E;
            sc[nt][2] = (mw >> (nt * 4 + 2)) & 1 ? MASK_L2 : sc[nt][2] * SCALE_L2E;
            sc[nt][3] = (mw >> (nt * 4 + 3)) & 1 ? MASK_L2 : sc[nt][3] * SCALE_L2E;
        }

        // ---- online softmax (log2 domain, ex2 on MUFU) ----
        float mx0 = sc[0][0], mx1 = sc[0][2];
#pragma unroll
        for (int nt = 0; nt < 8; nt++) {
            mx0 = fmaxf(mx0, fmaxf(sc[nt][0], sc[nt][1]));
            mx1 = fmaxf(mx1, fmaxf(sc[nt][2], sc[nt][3]));
        }
        mx0 = fmaxf(mx0, __shfl_xor_sync(0xFFFFFFFFu, mx0, 1));
        mx0 = fmaxf(mx0, __shfl_xor_sync(0xFFFFFFFFu, mx0, 2));
        mx1 = fmaxf(mx1, __shfl_xor_sync(0xFFFFFFFFu, mx1, 1));
        mx1 = fmaxf(mx1, __shfl_xor_sync(0xFFFFFFFFu, mx1, 2));

        const float nm0 = fmaxf(m0, mx0), nm1 = fmaxf(m1, mx1);
        const float cr0 = ex2(m0 - nm0), cr1 = ex2(m1 - nm1);
        m0 = nm0; m1 = nm1;

        float s0 = 0.0f, s1 = 0.0f;
#pragma unroll
        for (int nt = 0; nt < 8; nt++) {
            sc[nt][0] = ex2(sc[nt][0] - nm0); s0 += sc[nt][0];
            sc[nt][1] = ex2(sc[nt][1] - nm0); s0 += sc[nt][1];
            sc[nt][2] = ex2(sc[nt][2] - nm1); s1 += sc[nt][2];
            sc[nt][3] = ex2(sc[nt][3] - nm1); s1 += sc[nt][3];
        }
        s0 += __shfl_xor_sync(0xFFFFFFFFu, s0, 1);
        s0 += __shfl_xor_sync(0xFFFFFFFFu, s0, 2);
        s1 += __shfl_xor_sync(0xFFFFFFFFu, s1, 1);
        s1 += __shfl_xor_sync(0xFFFFFFFFu, s1, 2);
        lsum0 = lsum0 * cr0 + s0;
        lsum1 = lsum1 * cr1 + s1;
#pragma unroll
        for (int nt = 0; nt < 8; nt++) {
            acc[nt][0] *= cr0; acc[nt][1] *= cr0;
            acc[nt][2] *= cr1; acc[nt][3] *= cr1;
        }

        // ---- ctx += P V, two halves, software-pipelined V loads ----
#pragma unroll
        for (int half = 0; half < 2; half++) {
            uint32_t ph[2][4], pl[2][4];
#pragma unroll
            for (int k2 = 0; k2 < 2; k2++) {
                const int kt16 = half * 2 + k2;
                split_hilo(sc[2 * kt16][0],     sc[2 * kt16][1],     ph[k2][0], pl[k2][0]);
                split_hilo(sc[2 * kt16][2],     sc[2 * kt16][3],     ph[k2][1], pl[k2][1]);
                split_hilo(sc[2 * kt16 + 1][0], sc[2 * kt16 + 1][1], ph[k2][2], pl[k2][2]);
                split_hilo(sc[2 * kt16 + 1][2], sc[2 * kt16 + 1][3], ph[k2][3], pl[k2][3]);
            }
            uint32_t vh4[2][4], vl4[2][4];
            {
                const uint32_t a0 = st + 2 * A_ARR + (uint32_t)(half * 2 * 16) * 144 + vlane;
                ldmx4t(vh4[0], a0);
                ldmx4t(vl4[0], a0 + A_ARR);
            }
#pragma unroll
            for (int step = 0; step < 8; step++) {
                const int buf = step & 1;
                if (step < 7) {
                    const int sn = step + 1;
                    const uint32_t an = st + 2 * A_ARR
                        + (uint32_t)((half * 2 + (sn >> 2)) * 16) * 144 + (sn & 3) * 32 + vlane;
                    ldmx4t(vh4[buf ^ 1], an);
                    ldmx4t(vl4[buf ^ 1], an + A_ARR);
                }
                const int k2 = step >> 2, db = step & 3;
                float* c0 = acc[2 * db];
                float* c1 = acc[2 * db + 1];
                mma16816(c0, ph[k2], vh4[buf][0], vh4[buf][1]);
                mma16816(c0, pl[k2], vh4[buf][0], vh4[buf][1]);
                mma16816(c0, ph[k2], vl4[buf][0], vl4[buf][1]);
                mma16816(c1, ph[k2], vh4[buf][2], vh4[buf][3]);
                mma16816(c1, pl[k2], vh4[buf][2], vh4[buf][3]);
                mma16816(c1, ph[k2], vl4[buf][2], vl4[buf][3]);
            }
        }
    }

    // ---- normalize + write ctx as bf16 hi/lo ----
    const float i0 = 1.0f / lsum0, i1 = 1.0f / lsum1;
    const int srow = q0 + w * 16 + (l >> 2);
    const int colb = h * 64 + 2 * (l & 3);
#pragma unroll
    for (int nt = 0; nt < 8; nt++) {
        const int col = colb + nt * 8;
        uint32_t hiw, low;
        split_hilo(acc[nt][0] * i0, acc[nt][1] * i0, hiw, low);
        const size_t off0 = ((size_t)srow * 4 + b) * HID + col;
        *(uint32_t*)(ctxh + off0) = hiw;
        *(uint32_t*)(ctxl + off0) = low;
        split_hilo(acc[nt][2] * i1, acc[nt][3] * i1, hiw, low);
        const size_t off1 = ((size_t)(srow + 8) * 4 + b) * HID + col;
        *(uint32_t*)(ctxh + off1) = hiw;
        *(uint32_t*)(ctxl + off1) = low;
    }
}

// ---------------------------------------------------------------------------
// Launch
// ---------------------------------------------------------------------------
extern "C" void kernel_launch(void* const* d_in, const int* in_sizes, int n_in,
                              void* d_out, int out_size) {
    const float* hs      = (const float*)d_in[0];
    const void*  mask    = d_in[1];
    const float* W_qkv   = (const float*)d_in[2];
    const float* b_qkv   = (const float*)d_in[3];
    const float* W_dense = (const float*)d_in[4];
    const float* b_dense = (const float*)d_in[5];
    float* out = (float*)d_out;

    __nv_bfloat16 *pAh, *pAl, *pWqh, *pWql, *pWdh, *pWdl;
    __nv_bfloat16 *Qh, *Ql, *Kh, *Kl, *Vh, *Vl;
    uint32_t* maskbits;
    cudaGetSymbolAddress((void**)&pAh, g_pA_hi);
    cudaGetSymbolAddress((void**)&pAl, g_pA_lo);
    cudaGetSymbolAddress((void**)&pWqh, g_pWq_hi);
    cudaGetSymbolAddress((void**)&pWql, g_pWq_lo);
    cudaGetSymbolAddress((void**)&pWdh, g_pWd_hi);
    cudaGetSymbolAddress((void**)&pWdl, g_pWd_lo);
    cudaGetSymbolAddress((void**)&Qh, g_Qh);
    cudaGetSymbolAddress((void**)&Ql, g_Ql);
    cudaGetSymbolAddress((void**)&Kh, g_Kh);
    cudaGetSymbolAddress((void**)&Kl, g_Kl);
    cudaGetSymbolAddress((void**)&Vh, g_Vh);
    cudaGetSymbolAddress((void**)&Vl, g_Vl);
    cudaGetSymbolAddress((void**)&maskbits, g_mask_bits);

    cudaFuncSetAttribute(gemm_mma, cudaFuncAttributeMaxDynamicSharedMemorySize, GT_SMEM);
    cudaFuncSetAttribute(attention_mma, cudaFuncAttributeMaxDynamicSharedMemorySize, A_SMEM);

    // 0) mask dtype + fragment-layout bit conversion
    detect_mask_dtype<<<1, 32>>>((const int*)mask);
    convert_mask_frag<<<BATCH * 16 * 32, 256>>>(mask, maskbits);

    // 1) pack hs + W_qkv
    pack_hilo<<<(M_ROWS * HID / 4) / 256, 256>>>(hs, pAh, pAl);
    pack_hilo<<<(QKV_N * HID / 4) / 256, 256>>>(W_qkv, pWqh, pWql);

    // 2) QKV GEMM -> split bf16 hi/lo Q/K/V
    gemm_mma<<<dim3(QKV_N / 128, M_ROWS / 128), 256, GT_SMEM>>>(
        pAh, pAl, pWqh, pWql, b_qkv, nullptr, QKV_N, 1, Qh, Ql, Kh, Kl, Vh, Vl);

    // 3) tensor-core flash attention -> ctx hi/lo (into pA buffers)
    attention_mma<<<dim3(S_LEN / 128, BATCH * NHEADS), 256, A_SMEM>>>(
        maskbits, Qh, Ql, Kh, Kl, Vh, Vl, pAh, pAl);

    // 4) pack W_dense + dense GEMM -> out
    pack_hilo<<<(HID * HID / 4) / 256, 256>>>(W_dense, pWdh, pWdl);
    gemm_mma<<<dim3(HID / 128, M_ROWS / 128), 256, GT_SMEM>>>(
        pAh, pAl, pWdh, pWdl, b_dense, out, HID, 0,
        nullptr, nullptr, nullptr, nullptr, nullptr, nullptr);
}